// round 1
// baseline (speedup 1.0000x reference)
#include <cuda_runtime.h>
#include <math.h>

#define NN 12288
#define SS 4096
#define MM 16384
#define EE 393216
#define FF 256
#define CC 128
#define SLOPE 0.2f
#define HOFF 33554432   // 4096*8192, h output starts here

// ---------------- scratch (static device memory; no allocation) ----------------
__device__ float g_h  [NN*FF];
__device__ float g_h2 [NN*FF];
__device__ float g_xl [3][NN*FF];
__device__ float g_ea [3][MM*FF];
__device__ float g_m  [3][MM*FF];
__device__ float g_s1 [3][NN];
__device__ float g_s2 [3][MM];
__device__ float g_nmax[3][NN];
__device__ float g_nrs [3][NN];
__device__ int   g_noff[3][NN+1];
__device__ int   g_eoff[3][MM+1];
__device__ int   g_ncur[3][NN];
__device__ int   g_ecur[3][MM];
__device__ int   g_eiN [3][EE];   // ei values in node-CSR order
__device__ int   g_niE [3][EE];   // ni values in edge-CSR order
__device__ float g_Dinv[3][NN];
__device__ float g_Binv[3][MM];
__device__ float g_newg[2][SS*CC];
__device__ float g_xs  [2][SS*CC];

__device__ __forceinline__ float lk(float v){ return v >= 0.f ? v : SLOPE * v; }

// ---------------- setup: counting-sort CSR build ----------------
__global__ void k_zero(){
    int i = blockIdx.x * blockDim.x + threadIdx.x;
    if (i < 3*(NN+1)) ((int*)g_noff)[i] = 0;
    if (i < 3*(MM+1)) ((int*)g_eoff)[i] = 0;
    if (i < 3*NN)     ((float*)g_Dinv)[i] = 0.f;
}

__global__ void k_hist(const int* __restrict__ ni0, const int* __restrict__ ei0,
                       const int* __restrict__ ni1, const int* __restrict__ ei1,
                       const int* __restrict__ ni2, const int* __restrict__ ei2,
                       const float* __restrict__ hw){
    int idx = blockIdx.x * blockDim.x + threadIdx.x;
    if (idx >= 3*EE) return;
    int b = idx / EE, j = idx % EE;
    const int* ni = (b==0) ? ni0 : (b==1) ? ni1 : ni2;
    const int* ei = (b==0) ? ei0 : (b==1) ? ei1 : ei2;
    int n = ni[j], e = ei[j];
    atomicAdd(&g_noff[b][n+1], 1);
    atomicAdd(&g_eoff[b][e+1], 1);
    atomicAdd(&g_Dinv[b][n], hw[e]);   // D accumulation (inverted later)
}

__global__ void k_scan(){
    int bid = blockIdx.x;
    int *arr, *cur; int len;
    if (bid < 3){ arr = g_noff[bid];   cur = g_ncur[bid];   len = NN+1; }
    else        { arr = g_eoff[bid-3]; cur = g_ecur[bid-3]; len = MM+1; }
    __shared__ int sh[1024];
    int carry = 0;
    for (int base = 0; base < len; base += 1024){
        int i = base + threadIdx.x;
        int v = (i < len) ? arr[i] : 0;
        sh[threadIdx.x] = v; __syncthreads();
        for (int off = 1; off < 1024; off <<= 1){
            int t = (threadIdx.x >= off) ? sh[threadIdx.x - off] : 0;
            __syncthreads();
            sh[threadIdx.x] += t;
            __syncthreads();
        }
        int incl = sh[threadIdx.x] + carry;
        if (i < len){ arr[i] = incl; if (i < len-1) cur[i] = incl; }
        int tot = sh[1023];
        __syncthreads();
        carry += tot;
    }
}

__global__ void k_scatter(const int* __restrict__ ni0, const int* __restrict__ ei0,
                          const int* __restrict__ ni1, const int* __restrict__ ei1,
                          const int* __restrict__ ni2, const int* __restrict__ ei2){
    int idx = blockIdx.x * blockDim.x + threadIdx.x;
    if (idx >= 3*EE) return;
    int b = idx / EE, j = idx % EE;
    const int* ni = (b==0) ? ni0 : (b==1) ? ni1 : ni2;
    const int* ei = (b==0) ? ei0 : (b==1) ? ei1 : ei2;
    int n = ni[j], e = ei[j];
    int pn = atomicAdd(&g_ncur[b][n], 1); g_eiN[b][pn] = e;
    int pe = atomicAdd(&g_ecur[b][e], 1); g_niE[b][pe] = n;
}

__global__ void k_invert(){
    int i = blockIdx.x * blockDim.x + threadIdx.x;
    if (i < 3*NN){
        float d = ((float*)g_Dinv)[i];
        ((float*)g_Dinv)[i] = (d > 0.f) ? 1.f/d : 0.f;
    }
    if (i < 3*MM){
        int b = i / MM, e = i % MM;
        int c = g_eoff[b][e+1] - g_eoff[b][e];
        g_Binv[b][e] = (c > 0) ? 1.f/(float)c : 0.f;
    }
}

// ---------------- fp32 SIMT GEMM (NN): C = act(A@B + bias) ----------------
// BM=BN=128, BK=16, 256 threads, 8x8 microtile. M,N multiples of 128; K of 16.
__global__ void __launch_bounds__(256) k_gemm_nn(
    const float* __restrict__ A, const float* __restrict__ B,
    float* __restrict__ C, const float* __restrict__ bias,
    int M, int N, int K, int ldc,
    long long sAz, long long sBz, long long sCz, long long sbz, int act)
{
    __shared__ float As[16][128];
    __shared__ float Bs[16][128];
    int z = blockIdx.z;
    A += (size_t)z * sAz; B += (size_t)z * sBz; C += (size_t)z * sCz;
    if (bias) bias += (size_t)z * sbz;
    int bm = blockIdx.y * 128, bn = blockIdx.x * 128;
    int tid = threadIdx.x;
    int tx = tid & 15, ty = tid >> 4;
    float acc[8][8];
    #pragma unroll
    for (int i = 0; i < 8; i++)
        #pragma unroll
        for (int j = 0; j < 8; j++) acc[i][j] = 0.f;

    for (int kt = 0; kt < K; kt += 16){
        #pragma unroll
        for (int q = tid; q < 512; q += 256){
            int r = q >> 2, c = (q & 3) << 2;
            float4 v = *(const float4*)(A + (size_t)(bm + r) * K + kt + c);
            As[c+0][r] = v.x; As[c+1][r] = v.y; As[c+2][r] = v.z; As[c+3][r] = v.w;
        }
        #pragma unroll
        for (int q = tid; q < 512; q += 256){
            int r = q >> 5, c = (q & 31) << 2;
            *(float4*)&Bs[r][c] = *(const float4*)(B + (size_t)(kt + r) * N + bn + c);
        }
        __syncthreads();
        #pragma unroll
        for (int kk = 0; kk < 16; kk++){
            float a[8], bb[8];
            *(float4*)(a)    = *(float4*)&As[kk][ty*8];
            *(float4*)(a+4)  = *(float4*)&As[kk][ty*8+4];
            *(float4*)(bb)   = *(float4*)&Bs[kk][tx*8];
            *(float4*)(bb+4) = *(float4*)&Bs[kk][tx*8+4];
            #pragma unroll
            for (int i = 0; i < 8; i++)
                #pragma unroll
                for (int j = 0; j < 8; j++) acc[i][j] += a[i]*bb[j];
        }
        __syncthreads();
    }

    float bv[8];
    if (bias){
        *(float4*)(bv)   = *(const float4*)(bias + bn + tx*8);
        *(float4*)(bv+4) = *(const float4*)(bias + bn + tx*8 + 4);
    } else {
        #pragma unroll
        for (int j = 0; j < 8; j++) bv[j] = 0.f;
    }
    #pragma unroll
    for (int i = 0; i < 8; i++){
        size_t row = (size_t)(bm + ty*8 + i);
        #pragma unroll
        for (int jj = 0; jj < 2; jj++){
            float4 v;
            v.x = acc[i][jj*4+0] + bv[jj*4+0];
            v.y = acc[i][jj*4+1] + bv[jj*4+1];
            v.z = acc[i][jj*4+2] + bv[jj*4+2];
            v.w = acc[i][jj*4+3] + bv[jj*4+3];
            if (act){ v.x = lk(v.x); v.y = lk(v.y); v.z = lk(v.z); v.w = lk(v.w); }
            *(float4*)(C + row * ldc + bn + tx*8 + jj*4) = v;
        }
    }
}

// ---------------- fp32 SIMT GEMM (NT): C = A @ B^T ----------------
__global__ void __launch_bounds__(256) k_gemm_nt(
    const float* __restrict__ A, const float* __restrict__ B,
    float* __restrict__ C, int M, int N, int K, int ldc,
    long long sAz, long long sBz, long long sCz)
{
    __shared__ float As[16][128];
    __shared__ float Bs[16][128];
    int z = blockIdx.z;
    A += (size_t)z * sAz; B += (size_t)z * sBz; C += (size_t)z * sCz;
    int bm = blockIdx.y * 128, bn = blockIdx.x * 128;
    int tid = threadIdx.x;
    int tx = tid & 15, ty = tid >> 4;
    float acc[8][8];
    #pragma unroll
    for (int i = 0; i < 8; i++)
        #pragma unroll
        for (int j = 0; j < 8; j++) acc[i][j] = 0.f;

    for (int kt = 0; kt < K; kt += 16){
        #pragma unroll
        for (int q = tid; q < 512; q += 256){
            int r = q >> 2, c = (q & 3) << 2;
            float4 v = *(const float4*)(A + (size_t)(bm + r) * K + kt + c);
            As[c+0][r] = v.x; As[c+1][r] = v.y; As[c+2][r] = v.z; As[c+3][r] = v.w;
        }
        #pragma unroll
        for (int q = tid; q < 512; q += 256){
            int r = q >> 2, c = (q & 3) << 2;
            float4 v = *(const float4*)(B + (size_t)(bn + r) * K + kt + c);
            Bs[c+0][r] = v.x; Bs[c+1][r] = v.y; Bs[c+2][r] = v.z; Bs[c+3][r] = v.w;
        }
        __syncthreads();
        #pragma unroll
        for (int kk = 0; kk < 16; kk++){
            float a[8], bb[8];
            *(float4*)(a)    = *(float4*)&As[kk][ty*8];
            *(float4*)(a+4)  = *(float4*)&As[kk][ty*8+4];
            *(float4*)(bb)   = *(float4*)&Bs[kk][tx*8];
            *(float4*)(bb+4) = *(float4*)&Bs[kk][tx*8+4];
            #pragma unroll
            for (int i = 0; i < 8; i++)
                #pragma unroll
                for (int j = 0; j < 8; j++) acc[i][j] += a[i]*bb[j];
        }
        __syncthreads();
    }
    #pragma unroll
    for (int i = 0; i < 8; i++){
        size_t row = (size_t)(bm + ty*8 + i);
        #pragma unroll
        for (int jj = 0; jj < 2; jj++){
            float4 v;
            v.x = acc[i][jj*4+0]; v.y = acc[i][jj*4+1];
            v.z = acc[i][jj*4+2]; v.w = acc[i][jj*4+3];
            *(float4*)(C + row * ldc + bn + tx*8 + jj*4) = v;
        }
    }
}

// ---------------- attention scalars ----------------
// s1[b][n] = xl[b][n,:]·att[b][:256] ; s2[b][e] = ea[b][e,:]·att[b][256:]
__global__ void k_s1s2(const float* __restrict__ att){
    int w = (blockIdx.x * blockDim.x + threadIdx.x) >> 5;
    int lane = threadIdx.x & 31;
    if (w >= 3*(NN+MM)) return;
    int b = w / (NN+MM);
    int rr = w % (NN+MM);
    const float *vec, *av; float* out;
    if (rr < NN){ vec = g_xl[b] + (size_t)rr*FF; av = att + b*512;       out = &g_s1[b][rr]; }
    else { int e = rr - NN; vec = g_ea[b] + (size_t)e*FF; av = att + b*512 + 256; out = &g_s2[b][e]; }
    float4 v0 = ((const float4*)vec)[lane],    v1 = ((const float4*)vec)[32+lane];
    float4 a0 = ((const float4*)av)[lane],     a1 = ((const float4*)av)[32+lane];
    float s = v0.x*a0.x + v0.y*a0.y + v0.z*a0.z + v0.w*a0.w
            + v1.x*a1.x + v1.y*a1.y + v1.z*a1.z + v1.w*a1.w;
    #pragma unroll
    for (int o = 16; o; o >>= 1) s += __shfl_xor_sync(0xffffffffu, s, o);
    if (lane == 0) *out = s;
}

// ---------------- per-node softmax stats (max, 1/sum) ----------------
__global__ void k_stats(){
    int w = (blockIdx.x * blockDim.x + threadIdx.x) >> 5;
    int lane = threadIdx.x & 31;
    if (w >= 3*NN) return;
    int b = w / NN, n = w % NN;
    int beg = g_noff[b][n], end = g_noff[b][n+1];
    float s1n = g_s1[b][n];
    float mx = -1e30f;
    for (int p = beg + lane; p < end; p += 32){
        int e = g_eiN[b][p];
        mx = fmaxf(mx, lk(s1n + g_s2[b][e]));
    }
    #pragma unroll
    for (int o = 16; o; o >>= 1) mx = fmaxf(mx, __shfl_xor_sync(0xffffffffu, mx, o));
    float sum = 0.f;
    for (int p = beg + lane; p < end; p += 32){
        int e = g_eiN[b][p];
        sum += __expf(lk(s1n + g_s2[b][e]) - mx);
    }
    #pragma unroll
    for (int o = 16; o; o >>= 1) sum += __shfl_xor_sync(0xffffffffu, sum, o);
    if (lane == 0){
        if (end > beg){ g_nmax[b][n] = mx; g_nrs[b][n] = 1.f/sum; }
        else          { g_nmax[b][n] = 0.f; g_nrs[b][n] = 0.f; }
    }
}

// ---------------- edge pass: m[e] = Binv[e] * Σ alpha_j * xl[ni_j] ----------------
__global__ void k_edge(){
    int w = (blockIdx.x * blockDim.x + threadIdx.x) >> 5;
    int lane = threadIdx.x & 31;
    if (w >= 3*MM) return;
    int b = w / MM, e = w % MM;
    int beg = g_eoff[b][e], end = g_eoff[b][e+1];
    float s2e = g_s2[b][e];
    const float* xlb = g_xl[b];
    float4 acc0 = {0,0,0,0}, acc1 = {0,0,0,0};
    for (int base = beg; base < end; base += 32){
        int p = base + lane;
        int nrow = 0; float coef = 0.f;
        if (p < end){
            nrow = g_niE[b][p];
            float a = lk(g_s1[b][nrow] + s2e);
            coef = __expf(a - g_nmax[b][nrow]) * g_nrs[b][nrow];
        }
        int cnt = min(32, end - base);
        for (int t = 0; t < cnt; t++){
            int   r = __shfl_sync(0xffffffffu, nrow, t);
            float c = __shfl_sync(0xffffffffu, coef, t);
            const float4* row = (const float4*)(xlb + (size_t)r * FF);
            float4 x0 = row[lane], x1 = row[32+lane];
            acc0.x += c*x0.x; acc0.y += c*x0.y; acc0.z += c*x0.z; acc0.w += c*x0.w;
            acc1.x += c*x1.x; acc1.y += c*x1.y; acc1.z += c*x1.z; acc1.w += c*x1.w;
        }
    }
    float bi = g_Binv[b][e];
    float4 o0 = {bi*acc0.x, bi*acc0.y, bi*acc0.z, bi*acc0.w};
    float4 o1 = {bi*acc1.x, bi*acc1.y, bi*acc1.z, bi*acc1.w};
    float4* mr = (float4*)(g_m[b] + (size_t)e * FF);
    mr[lane] = o0; mr[32+lane] = o1;
}

// ---------------- node pass: h_out[n] = leaky( Σ_b Dinv*Σ alpha*m[ei] + Σ_b bias_b ) ----------------
__global__ void k_node(const float* __restrict__ bc, float* __restrict__ hout){
    int w = (blockIdx.x * blockDim.x + threadIdx.x) >> 5;
    int lane = threadIdx.x & 31;
    if (w >= NN) return;
    int n = w;
    float4 t0 = {0,0,0,0}, t1 = {0,0,0,0};
    #pragma unroll
    for (int b = 0; b < 3; b++){
        int beg = g_noff[b][n], end = g_noff[b][n+1];
        float s1n = g_s1[b][n], mxn = g_nmax[b][n], rsn = g_nrs[b][n];
        const float* mb = g_m[b];
        float4 a0 = {0,0,0,0}, a1 = {0,0,0,0};
        for (int base = beg; base < end; base += 32){
            int p = base + lane;
            int er = 0; float coef = 0.f;
            if (p < end){
                er = g_eiN[b][p];
                coef = __expf(lk(s1n + g_s2[b][er]) - mxn) * rsn;
            }
            int cnt = min(32, end - base);
            for (int t = 0; t < cnt; t++){
                int   r = __shfl_sync(0xffffffffu, er, t);
                float c = __shfl_sync(0xffffffffu, coef, t);
                const float4* row = (const float4*)(mb + (size_t)r * FF);
                float4 x0 = row[lane], x1 = row[32+lane];
                a0.x += c*x0.x; a0.y += c*x0.y; a0.z += c*x0.z; a0.w += c*x0.w;
                a1.x += c*x1.x; a1.y += c*x1.y; a1.z += c*x1.z; a1.w += c*x1.w;
            }
        }
        float di = g_Dinv[b][n];
        t0.x += di*a0.x; t0.y += di*a0.y; t0.z += di*a0.z; t0.w += di*a0.w;
        t1.x += di*a1.x; t1.y += di*a1.y; t1.z += di*a1.z; t1.w += di*a1.w;
    }
    #pragma unroll
    for (int k = 0; k < 3; k++){
        float4 b0 = ((const float4*)(bc + k*256))[lane];
        float4 b1 = ((const float4*)(bc + k*256))[32+lane];
        t0.x += b0.x; t0.y += b0.y; t0.z += b0.z; t0.w += b0.w;
        t1.x += b1.x; t1.y += b1.y; t1.z += b1.z; t1.w += b1.w;
    }
    t0.x = lk(t0.x); t0.y = lk(t0.y); t0.z = lk(t0.z); t0.w = lk(t0.w);
    t1.x = lk(t1.x); t1.y = lk(t1.y); t1.z = lk(t1.z); t1.w = lk(t1.w);
    float4* orow = (float4*)(hout + (size_t)n * FF);
    orow[lane] = t0; orow[32+lane] = t1;
}

// ---------------- host launcher ----------------
static void* symaddr(const void* sym){ void* p = nullptr; cudaGetSymbolAddress(&p, sym); return p; }

extern "C" void kernel_launch(void* const* d_in, const int* in_sizes, int n_in,
                              void* d_out, int out_size){
    const float* g   = (const float*)d_in[0];
    const float* x   = (const float*)d_in[1];
    const float* hw  = (const float*)d_in[2];
    const float* hA  = (const float*)d_in[3];
    const int* ni0 = (const int*)d_in[4]; const int* ei0 = (const int*)d_in[5];
    const int* ni1 = (const int*)d_in[6]; const int* ei1 = (const int*)d_in[7];
    const int* ni2 = (const int*)d_in[8]; const int* ei2 = (const int*)d_in[9];
    const float* W0  = (const float*)d_in[10]; const float* b0  = (const float*)d_in[11];
    const float* Wh1 = (const float*)d_in[12]; const float* at1 = (const float*)d_in[13];
    const float* bc1 = (const float*)d_in[14];
    const float* W1  = (const float*)d_in[15]; const float* b1  = (const float*)d_in[16];
    const float* Wh2 = (const float*)d_in[17]; const float* at2 = (const float*)d_in[18];
    const float* bc2 = (const float*)d_in[19];
    const float* Wg  = (const float*)d_in[20]; const float* bg  = (const float*)d_in[21];
    const float* Wx  = (const float*)d_in[22]; const float* bx  = (const float*)d_in[23];
    float* out = (float*)d_out;

    float* p_h    = (float*)symaddr(g_h);
    float* p_h2   = (float*)symaddr(g_h2);
    float* p_xl   = (float*)symaddr(g_xl);
    float* p_ea   = (float*)symaddr(g_ea);
    float* p_newg = (float*)symaddr(g_newg);
    float* p_xs   = (float*)symaddr(g_xs);

    // ---- setup: CSR build ----
    k_zero<<<(3*(MM+1) + 255)/256, 256>>>();
    k_hist<<<(3*EE + 255)/256, 256>>>(ni0, ei0, ni1, ei1, ni2, ei2, hw);
    k_scan<<<6, 1024>>>();
    k_scatter<<<(3*EE + 255)/256, 256>>>(ni0, ei0, ni1, ei1, ni2, ei2);
    k_invert<<<(3*MM + 255)/256, 256>>>();

    // ---- layer0: per-segment linear + leaky -> g_h ----
    k_gemm_nn<<<dim3(2,32,3), 256>>>(g, W0, p_h, b0, 4096, 256, 256, 256,
                                     (long long)4096*256, 65536LL, (long long)4096*256, 256LL, 1);

    // ---- hyper1 (reads g_h, writes g_h) ----
    k_gemm_nn<<<dim3(2,96,3), 256>>>(p_h, Wh1, p_xl, nullptr, 12288, 256, 256, 256,
                                     0LL, 65536LL, (long long)12288*256, 0LL, 0);
    k_gemm_nn<<<dim3(2,128,3), 256>>>(hA, Wh1, p_ea, nullptr, 16384, 256, 256, 256,
                                      0LL, 65536LL, (long long)16384*256, 0LL, 0);
    k_s1s2<<<(3*(NN+MM)*32 + 255)/256, 256>>>(at1);
    k_stats<<<(3*NN*32 + 255)/256, 256>>>();
    k_edge<<<(3*MM*32 + 255)/256, 256>>>();
    k_node<<<(NN*32 + 255)/256, 256>>>(bc1, p_h);

    // ---- layer1: per-segment linear + leaky -> g_h2 ----
    k_gemm_nn<<<dim3(2,32,3), 256>>>(p_h, W1, p_h2, b1, 4096, 256, 256, 256,
                                     (long long)4096*256, 65536LL, (long long)4096*256, 256LL, 1);

    // ---- hyper2 (reads g_h2, writes h directly into d_out[HOFF:]) ----
    k_gemm_nn<<<dim3(2,96,3), 256>>>(p_h2, Wh2, p_xl, nullptr, 12288, 256, 256, 256,
                                     0LL, 65536LL, (long long)12288*256, 0LL, 0);
    k_gemm_nn<<<dim3(2,128,3), 256>>>(hA, Wh2, p_ea, nullptr, 16384, 256, 256, 256,
                                      0LL, 65536LL, (long long)16384*256, 0LL, 0);
    k_s1s2<<<(3*(NN+MM)*32 + 255)/256, 256>>>(at2);
    k_stats<<<(3*NN*32 + 255)/256, 256>>>();
    k_edge<<<(3*MM*32 + 255)/256, 256>>>();
    k_node<<<(NN*32 + 255)/256, 256>>>(bc2, out + HOFF);

    // ---- projections (only segments i=1,2 are needed for the result) ----
    // new_g[z] = leaky(h[(z+1)*S : ] @ Wg[z+1] + bg[z+1]),  z in {0,1}
    k_gemm_nn<<<dim3(1,32,2), 256>>>(out + HOFF + (size_t)4096*256, Wg + 32768, p_newg, bg + 128,
                                     4096, 128, 256, 128,
                                     (long long)4096*256, 32768LL, (long long)4096*128, 128LL, 1);
    // xs[z] = leaky(x @ Wx[z+1] + bx[z+1])
    k_gemm_nn<<<dim3(1,32,2), 256>>>(x, Wx + 32768, p_xs, bx + 128,
                                     4096, 128, 256, 128,
                                     0LL, 32768LL, (long long)4096*128, 128LL, 1);

    // ---- result: [xs1@newg1^T | xs2@newg2^T] -> d_out[0 : 4096*8192] ----
    k_gemm_nt<<<dim3(32,32,2), 256>>>(p_xs, p_newg, out, 4096, 4096, 128, 8192,
                                      (long long)4096*128, (long long)4096*128, 4096LL);
}

// round 2
// speedup vs baseline: 1.5611x; 1.5611x over previous
#include <cuda_runtime.h>
#include <math.h>

#define NN 12288
#define SS 4096
#define MM 16384
#define EE 393216
#define FF 256
#define CC 128
#define SLOPE 0.2f
#define HOFF 33554432   // 4096*8192, h output starts here

// ---------------- scratch (static device memory; no allocation) ----------------
__device__ float g_h  [NN*FF];
__device__ float g_h2 [NN*FF];
__device__ float g_xl [3][NN*FF];
__device__ float g_ea [3][MM*FF];
__device__ float g_m  [3][MM*FF];
__device__ float g_s1 [3][NN];
__device__ float g_s2 [3][MM];
__device__ float g_nmax[3][NN];
__device__ float g_nrs [3][NN];
__device__ int   g_noff[3][NN+1];
__device__ int   g_eoff[3][MM+1];
__device__ int   g_ncur[3][NN];
__device__ int   g_ecur[3][MM];
__device__ int   g_eiN [3][EE];   // ei values in node-CSR order
__device__ int   g_niE [3][EE];   // ni values in edge-CSR order
__device__ float g_Dinv[3][NN];
__device__ float g_Binv[3][MM];
__device__ float g_newg[2][SS*CC];
__device__ float g_xs  [2][SS*CC];

__device__ __forceinline__ float lk(float v){ return v >= 0.f ? v : SLOPE * v; }

__device__ __forceinline__ unsigned f2tf(float f){
    unsigned u; asm("cvt.rna.tf32.f32 %0, %1;" : "=r"(u) : "f"(f)); return u;
}

// ---------------- setup: counting-sort CSR build ----------------
__global__ void k_zero(){
    int i = blockIdx.x * blockDim.x + threadIdx.x;
    if (i < 3*(NN+1)) ((int*)g_noff)[i] = 0;
    if (i < 3*(MM+1)) ((int*)g_eoff)[i] = 0;
    if (i < 3*NN)     ((float*)g_Dinv)[i] = 0.f;
}

__global__ void k_hist(const int* __restrict__ ni0, const int* __restrict__ ei0,
                       const int* __restrict__ ni1, const int* __restrict__ ei1,
                       const int* __restrict__ ni2, const int* __restrict__ ei2,
                       const float* __restrict__ hw){
    int idx = blockIdx.x * blockDim.x + threadIdx.x;
    if (idx >= 3*EE) return;
    int b = idx / EE, j = idx % EE;
    const int* ni = (b==0) ? ni0 : (b==1) ? ni1 : ni2;
    const int* ei = (b==0) ? ei0 : (b==1) ? ei1 : ei2;
    int n = ni[j], e = ei[j];
    atomicAdd(&g_noff[b][n+1], 1);
    atomicAdd(&g_eoff[b][e+1], 1);
    atomicAdd(&g_Dinv[b][n], hw[e]);
}

__global__ void k_scan(){
    int bid = blockIdx.x;
    int *arr, *cur; int len;
    if (bid < 3){ arr = g_noff[bid];   cur = g_ncur[bid];   len = NN+1; }
    else        { arr = g_eoff[bid-3]; cur = g_ecur[bid-3]; len = MM+1; }
    __shared__ int sh[1024];
    int carry = 0;
    for (int base = 0; base < len; base += 1024){
        int i = base + threadIdx.x;
        int v = (i < len) ? arr[i] : 0;
        sh[threadIdx.x] = v; __syncthreads();
        for (int off = 1; off < 1024; off <<= 1){
            int t = (threadIdx.x >= off) ? sh[threadIdx.x - off] : 0;
            __syncthreads();
            sh[threadIdx.x] += t;
            __syncthreads();
        }
        int incl = sh[threadIdx.x] + carry;
        if (i < len){ arr[i] = incl; if (i < len-1) cur[i] = incl; }
        int tot = sh[1023];
        __syncthreads();
        carry += tot;
    }
}

__global__ void k_scatter(const int* __restrict__ ni0, const int* __restrict__ ei0,
                          const int* __restrict__ ni1, const int* __restrict__ ei1,
                          const int* __restrict__ ni2, const int* __restrict__ ei2){
    int idx = blockIdx.x * blockDim.x + threadIdx.x;
    if (idx >= 3*EE) return;
    int b = idx / EE, j = idx % EE;
    const int* ni = (b==0) ? ni0 : (b==1) ? ni1 : ni2;
    const int* ei = (b==0) ? ei0 : (b==1) ? ei1 : ei2;
    int n = ni[j], e = ei[j];
    int pn = atomicAdd(&g_ncur[b][n], 1); g_eiN[b][pn] = e;
    int pe = atomicAdd(&g_ecur[b][e], 1); g_niE[b][pe] = n;
}

__global__ void k_invert(){
    int i = blockIdx.x * blockDim.x + threadIdx.x;
    if (i < 3*NN){
        float d = ((float*)g_Dinv)[i];
        ((float*)g_Dinv)[i] = (d > 0.f) ? 1.f/d : 0.f;
    }
    if (i < 3*MM){
        int b = i / MM, e = i % MM;
        int c = g_eoff[b][e+1] - g_eoff[b][e];
        g_Binv[b][e] = (c > 0) ? 1.f/(float)c : 0.f;
    }
}

// ---------------- tf32 tensor-core GEMM ----------------
// BM=BN=128, BK=16, 256 thr = 8 warps (4x2), warp tile 32x64, mma.m16n8k8.tf32
// NT=0: C = act(A[M,K] @ B[K,N] + bias)   NT=1: C = A[M,K] @ B[N,K]^T
template<int NT>
__global__ void __launch_bounds__(256) k_mma(
    const float* __restrict__ A, const float* __restrict__ B,
    float* __restrict__ C, const float* __restrict__ bias,
    int M, int N, int K, int ldc,
    long long sAz, long long sBz, long long sCz, long long sbz, int act)
{
    __shared__ unsigned As[16][136];
    __shared__ unsigned Bs[16][136];
    int z = blockIdx.z;
    A += (size_t)z * sAz; B += (size_t)z * sBz; C += (size_t)z * sCz;
    if (bias) bias += (size_t)z * sbz;
    int bm = blockIdx.y * 128, bn = blockIdx.x * 128;
    int tid = threadIdx.x;
    int warp = tid >> 5, lane = tid & 31;
    int wm = warp & 3, wn = warp >> 2;       // 4 x 2 warp grid
    int g = lane >> 2, tg = lane & 3;        // groupID, thread-in-group

    float c[2][8][4];
    #pragma unroll
    for (int mt = 0; mt < 2; mt++)
        #pragma unroll
        for (int nt = 0; nt < 8; nt++)
            #pragma unroll
            for (int i = 0; i < 4; i++) c[mt][nt][i] = 0.f;

    for (int kt = 0; kt < K; kt += 16){
        // A tile: As[k][m]
        #pragma unroll
        for (int q = tid; q < 512; q += 256){
            int r = q >> 2, cc = (q & 3) << 2;
            float4 v = *(const float4*)(A + (size_t)(bm + r) * K + kt + cc);
            As[cc+0][r] = f2tf(v.x); As[cc+1][r] = f2tf(v.y);
            As[cc+2][r] = f2tf(v.z); As[cc+3][r] = f2tf(v.w);
        }
        // B tile: Bs[k][n]
        if (NT){
            #pragma unroll
            for (int q = tid; q < 512; q += 256){
                int r = q >> 2, cc = (q & 3) << 2;
                float4 v = *(const float4*)(B + (size_t)(bn + r) * K + kt + cc);
                Bs[cc+0][r] = f2tf(v.x); Bs[cc+1][r] = f2tf(v.y);
                Bs[cc+2][r] = f2tf(v.z); Bs[cc+3][r] = f2tf(v.w);
            }
        } else {
            #pragma unroll
            for (int q = tid; q < 512; q += 256){
                int r = q >> 5, cc = (q & 31) << 2;
                float4 v = *(const float4*)(B + (size_t)(kt + r) * N + bn + cc);
                Bs[r][cc+0] = f2tf(v.x); Bs[r][cc+1] = f2tf(v.y);
                Bs[r][cc+2] = f2tf(v.z); Bs[r][cc+3] = f2tf(v.w);
            }
        }
        __syncthreads();

        #pragma unroll
        for (int ks = 0; ks < 2; ks++){
            int k0 = ks * 8;
            unsigned bf[8][2];
            #pragma unroll
            for (int nt = 0; nt < 8; nt++){
                int col = wn*64 + nt*8 + g;
                bf[nt][0] = Bs[k0+tg  ][col];
                bf[nt][1] = Bs[k0+tg+4][col];
            }
            #pragma unroll
            for (int mt = 0; mt < 2; mt++){
                int mb = wm*32 + mt*16;
                unsigned a0 = As[k0+tg  ][mb+g];
                unsigned a1 = As[k0+tg  ][mb+8+g];
                unsigned a2 = As[k0+tg+4][mb+g];
                unsigned a3 = As[k0+tg+4][mb+8+g];
                #pragma unroll
                for (int nt = 0; nt < 8; nt++){
                    asm volatile(
                        "mma.sync.aligned.m16n8k8.row.col.f32.tf32.tf32.f32 "
                        "{%0,%1,%2,%3}, {%4,%5,%6,%7}, {%8,%9}, {%0,%1,%2,%3};"
                        : "+f"(c[mt][nt][0]), "+f"(c[mt][nt][1]),
                          "+f"(c[mt][nt][2]), "+f"(c[mt][nt][3])
                        : "r"(a0), "r"(a1), "r"(a2), "r"(a3),
                          "r"(bf[nt][0]), "r"(bf[nt][1]));
                }
            }
        }
        __syncthreads();
    }

    // epilogue
    #pragma unroll
    for (int mt = 0; mt < 2; mt++){
        int row0 = bm + wm*32 + mt*16 + g;
        #pragma unroll
        for (int nt = 0; nt < 8; nt++){
            int col = bn + wn*64 + nt*8 + 2*tg;
            float b0 = 0.f, b1 = 0.f;
            if (bias){ b0 = bias[col]; b1 = bias[col+1]; }
            float2 v0, v1;
            v0.x = c[mt][nt][0] + b0; v0.y = c[mt][nt][1] + b1;
            v1.x = c[mt][nt][2] + b0; v1.y = c[mt][nt][3] + b1;
            if (act){ v0.x = lk(v0.x); v0.y = lk(v0.y); v1.x = lk(v1.x); v1.y = lk(v1.y); }
            *(float2*)(C + (size_t)row0 * ldc + col)       = v0;
            *(float2*)(C + (size_t)(row0 + 8) * ldc + col) = v1;
        }
    }
}

// ---------------- attention scalars ----------------
__global__ void k_s1s2(const float* __restrict__ att){
    int w = (blockIdx.x * blockDim.x + threadIdx.x) >> 5;
    int lane = threadIdx.x & 31;
    if (w >= 3*(NN+MM)) return;
    int b = w / (NN+MM);
    int rr = w % (NN+MM);
    const float *vec, *av; float* out;
    if (rr < NN){ vec = g_xl[b] + (size_t)rr*FF; av = att + b*512;       out = &g_s1[b][rr]; }
    else { int e = rr - NN; vec = g_ea[b] + (size_t)e*FF; av = att + b*512 + 256; out = &g_s2[b][e]; }
    float4 v0 = ((const float4*)vec)[lane],    v1 = ((const float4*)vec)[32+lane];
    float4 a0 = ((const float4*)av)[lane],     a1 = ((const float4*)av)[32+lane];
    float s = v0.x*a0.x + v0.y*a0.y + v0.z*a0.z + v0.w*a0.w
            + v1.x*a1.x + v1.y*a1.y + v1.z*a1.z + v1.w*a1.w;
    #pragma unroll
    for (int o = 16; o; o >>= 1) s += __shfl_xor_sync(0xffffffffu, s, o);
    if (lane == 0) *out = s;
}

// ---------------- per-node softmax stats (max, 1/sum) ----------------
__global__ void k_stats(){
    int w = (blockIdx.x * blockDim.x + threadIdx.x) >> 5;
    int lane = threadIdx.x & 31;
    if (w >= 3*NN) return;
    int b = w / NN, n = w % NN;
    int beg = g_noff[b][n], end = g_noff[b][n+1];
    float s1n = g_s1[b][n];
    float mx = -1e30f;
    for (int p = beg + lane; p < end; p += 32){
        int e = g_eiN[b][p];
        mx = fmaxf(mx, lk(s1n + g_s2[b][e]));
    }
    #pragma unroll
    for (int o = 16; o; o >>= 1) mx = fmaxf(mx, __shfl_xor_sync(0xffffffffu, mx, o));
    float sum = 0.f;
    for (int p = beg + lane; p < end; p += 32){
        int e = g_eiN[b][p];
        sum += __expf(lk(s1n + g_s2[b][e]) - mx);
    }
    #pragma unroll
    for (int o = 16; o; o >>= 1) sum += __shfl_xor_sync(0xffffffffu, sum, o);
    if (lane == 0){
        if (end > beg){ g_nmax[b][n] = mx; g_nrs[b][n] = 1.f/sum; }
        else          { g_nmax[b][n] = 0.f; g_nrs[b][n] = 0.f; }
    }
}

// ---------------- edge pass ----------------
__global__ void k_edge(){
    int w = (blockIdx.x * blockDim.x + threadIdx.x) >> 5;
    int lane = threadIdx.x & 31;
    if (w >= 3*MM) return;
    int b = w / MM, e = w % MM;
    int beg = g_eoff[b][e], end = g_eoff[b][e+1];
    float s2e = g_s2[b][e];
    const float* xlb = g_xl[b];
    float4 acc0 = {0,0,0,0}, acc1 = {0,0,0,0};
    for (int base = beg; base < end; base += 32){
        int p = base + lane;
        int nrow = 0; float coef = 0.f;
        if (p < end){
            nrow = g_niE[b][p];
            float a = lk(g_s1[b][nrow] + s2e);
            coef = __expf(a - g_nmax[b][nrow]) * g_nrs[b][nrow];
        }
        int cnt = min(32, end - base);
        for (int t = 0; t < cnt; t++){
            int   r = __shfl_sync(0xffffffffu, nrow, t);
            float c = __shfl_sync(0xffffffffu, coef, t);
            const float4* row = (const float4*)(xlb + (size_t)r * FF);
            float4 x0 = row[lane], x1 = row[32+lane];
            acc0.x += c*x0.x; acc0.y += c*x0.y; acc0.z += c*x0.z; acc0.w += c*x0.w;
            acc1.x += c*x1.x; acc1.y += c*x1.y; acc1.z += c*x1.z; acc1.w += c*x1.w;
        }
    }
    float bi = g_Binv[b][e];
    float4 o0 = {bi*acc0.x, bi*acc0.y, bi*acc0.z, bi*acc0.w};
    float4 o1 = {bi*acc1.x, bi*acc1.y, bi*acc1.z, bi*acc1.w};
    float4* mr = (float4*)(g_m[b] + (size_t)e * FF);
    mr[lane] = o0; mr[32+lane] = o1;
}

// ---------------- node pass ----------------
__global__ void k_node(const float* __restrict__ bc, float* __restrict__ hout){
    int w = (blockIdx.x * blockDim.x + threadIdx.x) >> 5;
    int lane = threadIdx.x & 31;
    if (w >= NN) return;
    int n = w;
    float4 t0 = {0,0,0,0}, t1 = {0,0,0,0};
    #pragma unroll
    for (int b = 0; b < 3; b++){
        int beg = g_noff[b][n], end = g_noff[b][n+1];
        float s1n = g_s1[b][n], mxn = g_nmax[b][n], rsn = g_nrs[b][n];
        const float* mb = g_m[b];
        float4 a0 = {0,0,0,0}, a1 = {0,0,0,0};
        for (int base = beg; base < end; base += 32){
            int p = base + lane;
            int er = 0; float coef = 0.f;
            if (p < end){
                er = g_eiN[b][p];
                coef = __expf(lk(s1n + g_s2[b][er]) - mxn) * rsn;
            }
            int cnt = min(32, end - base);
            for (int t = 0; t < cnt; t++){
                int   r = __shfl_sync(0xffffffffu, er, t);
                float c = __shfl_sync(0xffffffffu, coef, t);
                const float4* row = (const float4*)(mb + (size_t)r * FF);
                float4 x0 = row[lane], x1 = row[32+lane];
                a0.x += c*x0.x; a0.y += c*x0.y; a0.z += c*x0.z; a0.w += c*x0.w;
                a1.x += c*x1.x; a1.y += c*x1.y; a1.z += c*x1.z; a1.w += c*x1.w;
            }
        }
        float di = g_Dinv[b][n];
        t0.x += di*a0.x; t0.y += di*a0.y; t0.z += di*a0.z; t0.w += di*a0.w;
        t1.x += di*a1.x; t1.y += di*a1.y; t1.z += di*a1.z; t1.w += di*a1.w;
    }
    #pragma unroll
    for (int k = 0; k < 3; k++){
        float4 b0 = ((const float4*)(bc + k*256))[lane];
        float4 b1 = ((const float4*)(bc + k*256))[32+lane];
        t0.x += b0.x; t0.y += b0.y; t0.z += b0.z; t0.w += b0.w;
        t1.x += b1.x; t1.y += b1.y; t1.z += b1.z; t1.w += b1.w;
    }
    t0.x = lk(t0.x); t0.y = lk(t0.y); t0.z = lk(t0.z); t0.w = lk(t0.w);
    t1.x = lk(t1.x); t1.y = lk(t1.y); t1.z = lk(t1.z); t1.w = lk(t1.w);
    float4* orow = (float4*)(hout + (size_t)n * FF);
    orow[lane] = t0; orow[32+lane] = t1;
}

// ---------------- host launcher ----------------
static void* symaddr(const void* sym){ void* p = nullptr; cudaGetSymbolAddress(&p, sym); return p; }

extern "C" void kernel_launch(void* const* d_in, const int* in_sizes, int n_in,
                              void* d_out, int out_size){
    const float* g   = (const float*)d_in[0];
    const float* x   = (const float*)d_in[1];
    const float* hw  = (const float*)d_in[2];
    const float* hA  = (const float*)d_in[3];
    const int* ni0 = (const int*)d_in[4]; const int* ei0 = (const int*)d_in[5];
    const int* ni1 = (const int*)d_in[6]; const int* ei1 = (const int*)d_in[7];
    const int* ni2 = (const int*)d_in[8]; const int* ei2 = (const int*)d_in[9];
    const float* W0  = (const float*)d_in[10]; const float* b0  = (const float*)d_in[11];
    const float* Wh1 = (const float*)d_in[12]; const float* at1 = (const float*)d_in[13];
    const float* bc1 = (const float*)d_in[14];
    const float* W1  = (const float*)d_in[15]; const float* b1  = (const float*)d_in[16];
    const float* Wh2 = (const float*)d_in[17]; const float* at2 = (const float*)d_in[18];
    const float* bc2 = (const float*)d_in[19];
    const float* Wg  = (const float*)d_in[20]; const float* bg  = (const float*)d_in[21];
    const float* Wx  = (const float*)d_in[22]; const float* bx  = (const float*)d_in[23];
    float* out = (float*)d_out;

    float* p_h    = (float*)symaddr(g_h);
    float* p_h2   = (float*)symaddr(g_h2);
    float* p_xl   = (float*)symaddr(g_xl);
    float* p_ea   = (float*)symaddr(g_ea);
    float* p_newg = (float*)symaddr(g_newg);
    float* p_xs   = (float*)symaddr(g_xs);

    // ---- setup: CSR build ----
    k_zero<<<(3*(MM+1) + 255)/256, 256>>>();
    k_hist<<<(3*EE + 255)/256, 256>>>(ni0, ei0, ni1, ei1, ni2, ei2, hw);
    k_scan<<<6, 1024>>>();
    k_scatter<<<(3*EE + 255)/256, 256>>>(ni0, ei0, ni1, ei1, ni2, ei2);
    k_invert<<<(3*MM + 255)/256, 256>>>();

    // ---- layer0: per-segment linear + leaky -> g_h ----
    k_mma<0><<<dim3(2,32,3), 256>>>(g, W0, p_h, b0, 4096, 256, 256, 256,
                                    (long long)4096*256, 65536LL, (long long)4096*256, 256LL, 1);

    // ---- hyper1 ----
    k_mma<0><<<dim3(2,96,3), 256>>>(p_h, Wh1, p_xl, nullptr, 12288, 256, 256, 256,
                                    0LL, 65536LL, (long long)12288*256, 0LL, 0);
    k_mma<0><<<dim3(2,128,3), 256>>>(hA, Wh1, p_ea, nullptr, 16384, 256, 256, 256,
                                     0LL, 65536LL, (long long)16384*256, 0LL, 0);
    k_s1s2<<<(3*(NN+MM)*32 + 255)/256, 256>>>(at1);
    k_stats<<<(3*NN*32 + 255)/256, 256>>>();
    k_edge<<<(3*MM*32 + 255)/256, 256>>>();
    k_node<<<(NN*32 + 255)/256, 256>>>(bc1, p_h);

    // ---- layer1 ----
    k_mma<0><<<dim3(2,32,3), 256>>>(p_h, W1, p_h2, b1, 4096, 256, 256, 256,
                                    (long long)4096*256, 65536LL, (long long)4096*256, 256LL, 1);

    // ---- hyper2 (h -> d_out[HOFF:]) ----
    k_mma<0><<<dim3(2,96,3), 256>>>(p_h2, Wh2, p_xl, nullptr, 12288, 256, 256, 256,
                                    0LL, 65536LL, (long long)12288*256, 0LL, 0);
    k_mma<0><<<dim3(2,128,3), 256>>>(hA, Wh2, p_ea, nullptr, 16384, 256, 256, 256,
                                     0LL, 65536LL, (long long)16384*256, 0LL, 0);
    k_s1s2<<<(3*(NN+MM)*32 + 255)/256, 256>>>(at2);
    k_stats<<<(3*NN*32 + 255)/256, 256>>>();
    k_edge<<<(3*MM*32 + 255)/256, 256>>>();
    k_node<<<(NN*32 + 255)/256, 256>>>(bc2, out + HOFF);

    // ---- projections (segments 1,2 only) ----
    k_mma<0><<<dim3(1,32,2), 256>>>(out + HOFF + (size_t)4096*256, Wg + 32768, p_newg, bg + 128,
                                    4096, 128, 256, 128,
                                    (long long)4096*256, 32768LL, (long long)4096*128, 128LL, 1);
    k_mma<0><<<dim3(1,32,2), 256>>>(x, Wx + 32768, p_xs, bx + 128,
                                    4096, 128, 256, 128,
                                    0LL, 32768LL, (long long)4096*128, 128LL, 1);

    // ---- result: [xs1@newg1^T | xs2@newg2^T] ----
    k_mma<1><<<dim3(32,32,2), 256>>>(p_xs, p_newg, out, nullptr, 4096, 4096, 128, 8192,
                                     (long long)4096*128, (long long)4096*128, 4096LL, 0LL, 0);
}

// round 3
// speedup vs baseline: 2.0144x; 1.2903x over previous
#include <cuda_runtime.h>
#include <cuda_fp16.h>
#include <math.h>

#define NN 12288
#define SS 4096
#define MM 16384
#define EE 393216
#define FF 256
#define CC 128
#define SLOPE 0.2f
#define HOFF 33554432   // 4096*8192, h output starts here

// ---------------- scratch (static device memory; no allocation) ----------------
__device__ float  g_h  [NN*FF];
__device__ float  g_h2 [NN*FF];
__device__ __half g_xl [3][NN*FF];    // fp16 rows for gather
__device__ __half g_m  [3][MM*FF];    // fp16 rows for gather
__device__ float  g_w2 [3][FF];       // W @ att[256:]
__device__ float  g_s2 [3][MM];
__device__ float4 g_ninfo[3][NN];     // (s1, max, 1/sum, _)
__device__ int    g_noff[3][NN+1];
__device__ int    g_eoff[3][MM+1];
__device__ int    g_ncur[3][NN];
__device__ int    g_ecur[3][MM];
__device__ int    g_eiN [3][EE];      // ei values in node-CSR order
__device__ int    g_niE [3][EE];      // ni values in edge-CSR order
__device__ float  g_Dinv[3][NN];
__device__ float  g_Binv[3][MM];
__device__ float  g_newg[2][SS*CC];
__device__ float  g_xs  [2][SS*CC];

__device__ __forceinline__ float lk(float v){ return v >= 0.f ? v : SLOPE * v; }

__device__ __forceinline__ unsigned f2tf(float f){
    unsigned u; asm("cvt.rna.tf32.f32 %0, %1;" : "=r"(u) : "f"(f)); return u;
}

// ---------------- setup: counting-sort CSR build ----------------
__global__ void k_zero(){
    int i = blockIdx.x * blockDim.x + threadIdx.x;
    if (i < 3*(NN+1)) ((int*)g_noff)[i] = 0;
    if (i < 3*(MM+1)) ((int*)g_eoff)[i] = 0;
    if (i < 3*NN)     ((float*)g_Dinv)[i] = 0.f;
}

__global__ void k_hist(const int* __restrict__ ni0, const int* __restrict__ ei0,
                       const int* __restrict__ ni1, const int* __restrict__ ei1,
                       const int* __restrict__ ni2, const int* __restrict__ ei2,
                       const float* __restrict__ hw){
    int idx = blockIdx.x * blockDim.x + threadIdx.x;
    if (idx >= 3*EE) return;
    int b = idx / EE, j = idx % EE;
    const int* ni = (b==0) ? ni0 : (b==1) ? ni1 : ni2;
    const int* ei = (b==0) ? ei0 : (b==1) ? ei1 : ei2;
    int n = ni[j], e = ei[j];
    atomicAdd(&g_noff[b][n+1], 1);
    atomicAdd(&g_eoff[b][e+1], 1);
    atomicAdd(&g_Dinv[b][n], hw[e]);
}

__global__ void k_scan(){
    int bid = blockIdx.x;
    int *arr, *cur; int len;
    if (bid < 3){ arr = g_noff[bid];   cur = g_ncur[bid];   len = NN+1; }
    else        { arr = g_eoff[bid-3]; cur = g_ecur[bid-3]; len = MM+1; }
    __shared__ int sh[1024];
    int carry = 0;
    for (int base = 0; base < len; base += 1024){
        int i = base + threadIdx.x;
        int v = (i < len) ? arr[i] : 0;
        sh[threadIdx.x] = v; __syncthreads();
        for (int off = 1; off < 1024; off <<= 1){
            int t = (threadIdx.x >= off) ? sh[threadIdx.x - off] : 0;
            __syncthreads();
            sh[threadIdx.x] += t;
            __syncthreads();
        }
        int incl = sh[threadIdx.x] + carry;
        if (i < len){ arr[i] = incl; if (i < len-1) cur[i] = incl; }
        int tot = sh[1023];
        __syncthreads();
        carry += tot;
    }
}

__global__ void k_scatter(const int* __restrict__ ni0, const int* __restrict__ ei0,
                          const int* __restrict__ ni1, const int* __restrict__ ei1,
                          const int* __restrict__ ni2, const int* __restrict__ ei2){
    int idx = blockIdx.x * blockDim.x + threadIdx.x;
    if (idx >= 3*EE) return;
    int b = idx / EE, j = idx % EE;
    const int* ni = (b==0) ? ni0 : (b==1) ? ni1 : ni2;
    const int* ei = (b==0) ? ei0 : (b==1) ? ei1 : ei2;
    int n = ni[j], e = ei[j];
    int pn = atomicAdd(&g_ncur[b][n], 1); g_eiN[b][pn] = e;
    int pe = atomicAdd(&g_ecur[b][e], 1); g_niE[b][pe] = n;
}

__global__ void k_invert(){
    int i = blockIdx.x * blockDim.x + threadIdx.x;
    if (i < 3*NN){
        float d = ((float*)g_Dinv)[i];
        ((float*)g_Dinv)[i] = (d > 0.f) ? 1.f/d : 0.f;
    }
    if (i < 3*MM){
        int b = i / MM, e = i % MM;
        int c = g_eoff[b][e+1] - g_eoff[b][e];
        g_Binv[b][e] = (c > 0) ? 1.f/(float)c : 0.f;
    }
}

// ---------------- tf32 tensor-core GEMM ----------------
// BM=BN=128, BK=16, 256 thr = 8 warps (4x2), warp tile 32x64, mma.m16n8k8.tf32
// NT=0: C = act(A[M,K]@B[K,N]+bias)  NT=1: C = A[M,K]@B[N,K]^T
// OUTH=1: write C as __half
template<int NT, int OUTH>
__global__ void __launch_bounds__(256) k_mma(
    const float* __restrict__ A, const float* __restrict__ B,
    void* __restrict__ Cv, const float* __restrict__ bias,
    int M, int N, int K, int ldc,
    long long sAz, long long sBz, long long sCz, long long sbz, int act)
{
    __shared__ unsigned As[16][136];
    __shared__ unsigned Bs[16][136];
    int z = blockIdx.z;
    A += (size_t)z * sAz; B += (size_t)z * sBz;
    if (bias) bias += (size_t)z * sbz;
    int bm = blockIdx.y * 128, bn = blockIdx.x * 128;
    int tid = threadIdx.x;
    int warp = tid >> 5, lane = tid & 31;
    int wm = warp & 3, wn = warp >> 2;
    int g = lane >> 2, tg = lane & 3;

    float c[2][8][4];
    #pragma unroll
    for (int mt = 0; mt < 2; mt++)
        #pragma unroll
        for (int nt = 0; nt < 8; nt++)
            #pragma unroll
            for (int i = 0; i < 4; i++) c[mt][nt][i] = 0.f;

    for (int kt = 0; kt < K; kt += 16){
        #pragma unroll
        for (int q = tid; q < 512; q += 256){
            int r = q >> 2, cc = (q & 3) << 2;
            float4 v = *(const float4*)(A + (size_t)(bm + r) * K + kt + cc);
            As[cc+0][r] = f2tf(v.x); As[cc+1][r] = f2tf(v.y);
            As[cc+2][r] = f2tf(v.z); As[cc+3][r] = f2tf(v.w);
        }
        if (NT){
            #pragma unroll
            for (int q = tid; q < 512; q += 256){
                int r = q >> 2, cc = (q & 3) << 2;
                float4 v = *(const float4*)(B + (size_t)(bn + r) * K + kt + cc);
                Bs[cc+0][r] = f2tf(v.x); Bs[cc+1][r] = f2tf(v.y);
                Bs[cc+2][r] = f2tf(v.z); Bs[cc+3][r] = f2tf(v.w);
            }
        } else {
            #pragma unroll
            for (int q = tid; q < 512; q += 256){
                int r = q >> 5, cc = (q & 31) << 2;
                float4 v = *(const float4*)(B + (size_t)(kt + r) * N + bn + cc);
                Bs[r][cc+0] = f2tf(v.x); Bs[r][cc+1] = f2tf(v.y);
                Bs[r][cc+2] = f2tf(v.z); Bs[r][cc+3] = f2tf(v.w);
            }
        }
        __syncthreads();

        #pragma unroll
        for (int ks = 0; ks < 2; ks++){
            int k0 = ks * 8;
            unsigned bf[8][2];
            #pragma unroll
            for (int nt = 0; nt < 8; nt++){
                int col = wn*64 + nt*8 + g;
                bf[nt][0] = Bs[k0+tg  ][col];
                bf[nt][1] = Bs[k0+tg+4][col];
            }
            #pragma unroll
            for (int mt = 0; mt < 2; mt++){
                int mb = wm*32 + mt*16;
                unsigned a0 = As[k0+tg  ][mb+g];
                unsigned a1 = As[k0+tg  ][mb+8+g];
                unsigned a2 = As[k0+tg+4][mb+g];
                unsigned a3 = As[k0+tg+4][mb+8+g];
                #pragma unroll
                for (int nt = 0; nt < 8; nt++){
                    asm volatile(
                        "mma.sync.aligned.m16n8k8.row.col.f32.tf32.tf32.f32 "
                        "{%0,%1,%2,%3}, {%4,%5,%6,%7}, {%8,%9}, {%0,%1,%2,%3};"
                        : "+f"(c[mt][nt][0]), "+f"(c[mt][nt][1]),
                          "+f"(c[mt][nt][2]), "+f"(c[mt][nt][3])
                        : "r"(a0), "r"(a1), "r"(a2), "r"(a3),
                          "r"(bf[nt][0]), "r"(bf[nt][1]));
                }
            }
        }
        __syncthreads();
    }

    #pragma unroll
    for (int mt = 0; mt < 2; mt++){
        int row0 = bm + wm*32 + mt*16 + g;
        #pragma unroll
        for (int nt = 0; nt < 8; nt++){
            int col = bn + wn*64 + nt*8 + 2*tg;
            float b0 = 0.f, b1 = 0.f;
            if (bias){ b0 = bias[col]; b1 = bias[col+1]; }
            float2 v0, v1;
            v0.x = c[mt][nt][0] + b0; v0.y = c[mt][nt][1] + b1;
            v1.x = c[mt][nt][2] + b0; v1.y = c[mt][nt][3] + b1;
            if (act){ v0.x = lk(v0.x); v0.y = lk(v0.y); v1.x = lk(v1.x); v1.y = lk(v1.y); }
            if (OUTH){
                __half* C = (__half*)Cv + (size_t)blockIdx.z * sCz;
                *(__half2*)(C + (size_t)row0 * ldc + col)       = __floats2half2_rn(v0.x, v0.y);
                *(__half2*)(C + (size_t)(row0 + 8) * ldc + col) = __floats2half2_rn(v1.x, v1.y);
            } else {
                float* C = (float*)Cv + (size_t)blockIdx.z * sCz;
                *(float2*)(C + (size_t)row0 * ldc + col)       = v0;
                *(float2*)(C + (size_t)(row0 + 8) * ldc + col) = v1;
            }
        }
    }
}

// ---------------- w2[b] = Wh[b] @ att[b][256:512]  (row-dot) ----------------
__global__ void k_watt(const float* __restrict__ Wh, const float* __restrict__ att){
    int w = (blockIdx.x * blockDim.x + threadIdx.x) >> 5;
    int lane = threadIdx.x & 31;
    if (w >= 3*FF) return;
    int b = w / FF, k = w % FF;
    const float* row = Wh + (size_t)b*FF*FF + (size_t)k*FF;
    const float* a2  = att + b*512 + 256;
    float4 r0 = ((const float4*)row)[lane*2], r1 = ((const float4*)row)[lane*2+1];
    float4 a0 = ((const float4*)a2 )[lane*2], a1 = ((const float4*)a2 )[lane*2+1];
    float s = r0.x*a0.x + r0.y*a0.y + r0.z*a0.z + r0.w*a0.w
            + r1.x*a1.x + r1.y*a1.y + r1.z*a1.z + r1.w*a1.w;
    #pragma unroll
    for (int o = 16; o; o >>= 1) s += __shfl_xor_sync(0xffffffffu, s, o);
    if (lane == 0) g_w2[b][k] = s;
}

// ---------------- s2[b][e] = hA[e] . w2[b] ----------------
__global__ void k_s2(const float* __restrict__ hA){
    int w = (blockIdx.x * blockDim.x + threadIdx.x) >> 5;
    int lane = threadIdx.x & 31;
    if (w >= 3*MM) return;
    int b = w / MM, e = w % MM;
    const float* row = hA + (size_t)e*FF;
    const float* w2  = g_w2[b];
    float4 r0 = ((const float4*)row)[lane*2], r1 = ((const float4*)row)[lane*2+1];
    float4 a0 = ((const float4*)w2 )[lane*2], a1 = ((const float4*)w2 )[lane*2+1];
    float s = r0.x*a0.x + r0.y*a0.y + r0.z*a0.z + r0.w*a0.w
            + r1.x*a1.x + r1.y*a1.y + r1.z*a1.z + r1.w*a1.w;
    #pragma unroll
    for (int o = 16; o; o >>= 1) s += __shfl_xor_sync(0xffffffffu, s, o);
    if (lane == 0) g_s2[b][e] = s;
}

// ---------------- stats: s1 + per-node softmax (max, 1/sum) -> ninfo ----------------
__global__ void k_stats(const float* __restrict__ att){
    int w = (blockIdx.x * blockDim.x + threadIdx.x) >> 5;
    int lane = threadIdx.x & 31;
    if (w >= 3*NN) return;
    int b = w / NN, n = w % NN;

    // s1 = xl[n] . att[b][:256]  (xl fp16)
    const __half* xr = g_xl[b] + (size_t)n*FF;
    float4 raw = ((const float4*)xr)[lane];
    const __half2* hp = (const __half2*)&raw;
    const float* a1p = att + b*512 + lane*8;
    float4 a0 = *(const float4*)a1p, a1 = *(const float4*)(a1p+4);
    float2 f0 = __half22float2(hp[0]), f1 = __half22float2(hp[1]);
    float2 f2 = __half22float2(hp[2]), f3 = __half22float2(hp[3]);
    float s1n = f0.x*a0.x + f0.y*a0.y + f1.x*a0.z + f1.y*a0.w
              + f2.x*a1.x + f2.y*a1.y + f3.x*a1.z + f3.y*a1.w;
    #pragma unroll
    for (int o = 16; o; o >>= 1) s1n += __shfl_xor_sync(0xffffffffu, s1n, o);

    int beg = g_noff[b][n], end = g_noff[b][n+1];
    float mx = -1e30f;
    for (int p = beg + lane; p < end; p += 32){
        int e = g_eiN[b][p];
        mx = fmaxf(mx, lk(s1n + g_s2[b][e]));
    }
    #pragma unroll
    for (int o = 16; o; o >>= 1) mx = fmaxf(mx, __shfl_xor_sync(0xffffffffu, mx, o));
    float sum = 0.f;
    for (int p = beg + lane; p < end; p += 32){
        int e = g_eiN[b][p];
        sum += __expf(lk(s1n + g_s2[b][e]) - mx);
    }
    #pragma unroll
    for (int o = 16; o; o >>= 1) sum += __shfl_xor_sync(0xffffffffu, sum, o);
    if (lane == 0){
        if (end > beg) g_ninfo[b][n] = make_float4(s1n, mx, 1.f/sum, 0.f);
        else           g_ninfo[b][n] = make_float4(s1n, 0.f, 0.f, 0.f);
    }
}

// ---------------- edge pass: m[e] = Binv * sum alpha * xl[ni]  (fp16 in/out) ----------------
__global__ void k_edge(){
    int w = (blockIdx.x * blockDim.x + threadIdx.x) >> 5;
    int lane = threadIdx.x & 31;
    if (w >= 3*MM) return;
    int b = w / MM, e = w % MM;
    int beg = g_eoff[b][e], end = g_eoff[b][e+1];
    float s2e = g_s2[b][e];
    const __half* xlb = g_xl[b];
    float acc[8] = {0,0,0,0,0,0,0,0};
    for (int base = beg; base < end; base += 32){
        int p = base + lane;
        int nrow = 0; float coef = 0.f;
        if (p < end){
            nrow = g_niE[b][p];
            float4 info = g_ninfo[b][nrow];
            coef = __expf(lk(info.x + s2e) - info.y) * info.z;
        }
        int cnt = min(32, end - base);
        for (int t = 0; t < cnt; t++){
            int   r = __shfl_sync(0xffffffffu, nrow, t);
            float c = __shfl_sync(0xffffffffu, coef, t);
            float4 raw = *(const float4*)(xlb + (size_t)r * FF + lane*8);
            const __half2* hp = (const __half2*)&raw;
            float2 f0 = __half22float2(hp[0]), f1 = __half22float2(hp[1]);
            float2 f2 = __half22float2(hp[2]), f3 = __half22float2(hp[3]);
            acc[0] += c*f0.x; acc[1] += c*f0.y; acc[2] += c*f1.x; acc[3] += c*f1.y;
            acc[4] += c*f2.x; acc[5] += c*f2.y; acc[6] += c*f3.x; acc[7] += c*f3.y;
        }
    }
    float bi = g_Binv[b][e];
    __half2 o[4];
    o[0] = __floats2half2_rn(bi*acc[0], bi*acc[1]);
    o[1] = __floats2half2_rn(bi*acc[2], bi*acc[3]);
    o[2] = __floats2half2_rn(bi*acc[4], bi*acc[5]);
    o[3] = __floats2half2_rn(bi*acc[6], bi*acc[7]);
    *(float4*)(g_m[b] + (size_t)e * FF + lane*8) = *(float4*)o;
}

// ---------------- node pass: h_out = leaky( sum_b Dinv*sum alpha*m[ei] + sum_b bias ) ----------------
__global__ void k_node(const float* __restrict__ bc, float* __restrict__ hout){
    int w = (blockIdx.x * blockDim.x + threadIdx.x) >> 5;
    int lane = threadIdx.x & 31;
    if (w >= NN) return;
    int n = w;
    float t[8] = {0,0,0,0,0,0,0,0};
    #pragma unroll
    for (int b = 0; b < 3; b++){
        int beg = g_noff[b][n], end = g_noff[b][n+1];
        float4 info = g_ninfo[b][n];
        float s1n = info.x, mxn = info.y, rsn = info.z;
        const __half* mb = g_m[b];
        float a[8] = {0,0,0,0,0,0,0,0};
        for (int base = beg; base < end; base += 32){
            int p = base + lane;
            int er = 0; float coef = 0.f;
            if (p < end){
                er = g_eiN[b][p];
                coef = __expf(lk(s1n + g_s2[b][er]) - mxn) * rsn;
            }
            int cnt = min(32, end - base);
            for (int t2 = 0; t2 < cnt; t2++){
                int   r = __shfl_sync(0xffffffffu, er, t2);
                float c = __shfl_sync(0xffffffffu, coef, t2);
                float4 raw = *(const float4*)(mb + (size_t)r * FF + lane*8);
                const __half2* hp = (const __half2*)&raw;
                float2 f0 = __half22float2(hp[0]), f1 = __half22float2(hp[1]);
                float2 f2 = __half22float2(hp[2]), f3 = __half22float2(hp[3]);
                a[0] += c*f0.x; a[1] += c*f0.y; a[2] += c*f1.x; a[3] += c*f1.y;
                a[4] += c*f2.x; a[5] += c*f2.y; a[6] += c*f3.x; a[7] += c*f3.y;
            }
        }
        float di = g_Dinv[b][n];
        #pragma unroll
        for (int i = 0; i < 8; i++) t[i] += di * a[i];
    }
    #pragma unroll
    for (int k = 0; k < 3; k++){
        float4 b0 = *(const float4*)(bc + k*256 + lane*8);
        float4 b1 = *(const float4*)(bc + k*256 + lane*8 + 4);
        t[0] += b0.x; t[1] += b0.y; t[2] += b0.z; t[3] += b0.w;
        t[4] += b1.x; t[5] += b1.y; t[6] += b1.z; t[7] += b1.w;
    }
    #pragma unroll
    for (int i = 0; i < 8; i++) t[i] = lk(t[i]);
    *(float4*)(hout + (size_t)n * FF + lane*8)     = make_float4(t[0], t[1], t[2], t[3]);
    *(float4*)(hout + (size_t)n * FF + lane*8 + 4) = make_float4(t[4], t[5], t[6], t[7]);
}

// ---------------- host launcher ----------------
static void* symaddr(const void* sym){ void* p = nullptr; cudaGetSymbolAddress(&p, sym); return p; }

extern "C" void kernel_launch(void* const* d_in, const int* in_sizes, int n_in,
                              void* d_out, int out_size){
    const float* g   = (const float*)d_in[0];
    const float* x   = (const float*)d_in[1];
    const float* hw  = (const float*)d_in[2];
    const float* hA  = (const float*)d_in[3];
    const int* ni0 = (const int*)d_in[4]; const int* ei0 = (const int*)d_in[5];
    const int* ni1 = (const int*)d_in[6]; const int* ei1 = (const int*)d_in[7];
    const int* ni2 = (const int*)d_in[8]; const int* ei2 = (const int*)d_in[9];
    const float* W0  = (const float*)d_in[10]; const float* b0  = (const float*)d_in[11];
    const float* Wh1 = (const float*)d_in[12]; const float* at1 = (const float*)d_in[13];
    const float* bc1 = (const float*)d_in[14];
    const float* W1  = (const float*)d_in[15]; const float* b1  = (const float*)d_in[16];
    const float* Wh2 = (const float*)d_in[17]; const float* at2 = (const float*)d_in[18];
    const float* bc2 = (const float*)d_in[19];
    const float* Wg  = (const float*)d_in[20]; const float* bg  = (const float*)d_in[21];
    const float* Wx  = (const float*)d_in[22]; const float* bx  = (const float*)d_in[23];
    float* out = (float*)d_out;

    float* p_h    = (float*)symaddr(g_h);
    float* p_h2   = (float*)symaddr(g_h2);
    void*  p_xl   = symaddr(g_xl);
    float* p_newg = (float*)symaddr(g_newg);
    float* p_xs   = (float*)symaddr(g_xs);

    // ---- setup: CSR build ----
    k_zero<<<(3*(MM+1) + 255)/256, 256>>>();
    k_hist<<<(3*EE + 255)/256, 256>>>(ni0, ei0, ni1, ei1, ni2, ei2, hw);
    k_scan<<<6, 1024>>>();
    k_scatter<<<(3*EE + 255)/256, 256>>>(ni0, ei0, ni1, ei1, ni2, ei2);
    k_invert<<<(3*MM + 255)/256, 256>>>();

    // ---- layer0: per-segment linear + leaky -> g_h ----
    k_mma<0,0><<<dim3(2,32,3), 256>>>(g, W0, p_h, b0, 4096, 256, 256, 256,
                                      (long long)4096*256, 65536LL, (long long)4096*256, 256LL, 1);

    // ---- hyper1 ----
    k_mma<0,1><<<dim3(2,96,3), 256>>>(p_h, Wh1, p_xl, nullptr, 12288, 256, 256, 256,
                                      0LL, 65536LL, (long long)12288*256, 0LL, 0);
    k_watt<<<(3*FF*32 + 255)/256, 256>>>(Wh1, at1);
    k_s2<<<(3*MM*32 + 255)/256, 256>>>(hA);
    k_stats<<<(3*NN*32 + 255)/256, 256>>>(at1);
    k_edge<<<(3*MM*32 + 255)/256, 256>>>();
    k_node<<<(NN*32 + 255)/256, 256>>>(bc1, p_h);

    // ---- layer1 ----
    k_mma<0,0><<<dim3(2,32,3), 256>>>(p_h, W1, p_h2, b1, 4096, 256, 256, 256,
                                      (long long)4096*256, 65536LL, (long long)4096*256, 256LL, 1);

    // ---- hyper2 (h -> d_out[HOFF:]) ----
    k_mma<0,1><<<dim3(2,96,3), 256>>>(p_h2, Wh2, p_xl, nullptr, 12288, 256, 256, 256,
                                      0LL, 65536LL, (long long)12288*256, 0LL, 0);
    k_watt<<<(3*FF*32 + 255)/256, 256>>>(Wh2, at2);
    k_s2<<<(3*MM*32 + 255)/256, 256>>>(hA);
    k_stats<<<(3*NN*32 + 255)/256, 256>>>(at2);
    k_edge<<<(3*MM*32 + 255)/256, 256>>>();
    k_node<<<(NN*32 + 255)/256, 256>>>(bc2, out + HOFF);

    // ---- projections (segments 1,2 only) ----
    k_mma<0,0><<<dim3(1,32,2), 256>>>(out + HOFF + (size_t)4096*256, Wg + 32768, p_newg, bg + 128,
                                      4096, 128, 256, 128,
                                      (long long)4096*256, 32768LL, (long long)4096*128, 128LL, 1);
    k_mma<0,0><<<dim3(1,32,2), 256>>>(x, Wx + 32768, p_xs, bx + 128,
                                      4096, 128, 256, 128,
                                      0LL, 32768LL, (long long)4096*128, 128LL, 1);

    // ---- result: [xs1@newg1^T | xs2@newg2^T] ----
    k_mma<1,0><<<dim3(32,32,2), 256>>>(p_xs, p_newg, out, nullptr, 4096, 4096, 128, 8192,
                                       (long long)4096*128, (long long)4096*128, 4096LL, 0LL, 0);
}

// round 5
// speedup vs baseline: 2.3673x; 1.1752x over previous
#include <cuda_runtime.h>
#include <cuda_fp16.h>
#include <math.h>

#define NN 12288
#define SS 4096
#define MM 16384
#define EE 393216
#define FF 256
#define CC 128
#define SLOPE 0.2f
#define HOFF 33554432   // 4096*8192, h output starts here

// ---------------- scratch (static device memory; no allocation) ----------------
__device__ float  g_h  [NN*FF];
__device__ float  g_h2 [NN*FF];
__device__ __half g_xl [3][NN*FF];    // fp16 rows for gather
__device__ __half g_m  [3][MM*FF];    // fp16 rows for gather
__device__ float  g_w2 [2][3][FF];    // W @ att[256:], per layer
__device__ float  g_s2 [2][3][MM];    // per layer
__device__ float4 g_ninfo[3][NN];     // (s1, max, 1/sum, _)
__device__ int    g_noff[3][NN+1];
__device__ int    g_eoff[3][MM+1];
__device__ int    g_ncur[3][NN];
__device__ int    g_ecur[3][MM];
__device__ int    g_eiN [3][EE];
__device__ int    g_niE [3][EE];
__device__ float  g_Dinv[3][NN];
__device__ float  g_Binv[3][MM];
__device__ float  g_newg[2][SS*CC];
__device__ float  g_xs  [2][SS*CC];

__device__ __forceinline__ float lk(float v){ return v >= 0.f ? v : SLOPE * v; }

__device__ __forceinline__ unsigned f2tf(float f){
    unsigned u; asm("cvt.rna.tf32.f32 %0, %1;" : "=r"(u) : "f"(f)); return u;
}
__device__ __forceinline__ unsigned packh2(float x, float y){
    __half2 h = __floats2half2_rn(x, y);
    return *(unsigned*)&h;
}

// ---------------- setup: counting-sort CSR build ----------------
__global__ void k_zero(){
    int i = blockIdx.x * blockDim.x + threadIdx.x;
    if (i < 3*(NN+1)) ((int*)g_noff)[i] = 0;
    if (i < 3*(MM+1)) ((int*)g_eoff)[i] = 0;
    if (i < 3*NN)     ((float*)g_Dinv)[i] = 0.f;
}

__global__ void k_hist(const int* __restrict__ ni0, const int* __restrict__ ei0,
                       const int* __restrict__ ni1, const int* __restrict__ ei1,
                       const int* __restrict__ ni2, const int* __restrict__ ei2,
                       const float* __restrict__ hw){
    int idx = blockIdx.x * blockDim.x + threadIdx.x;
    if (idx >= 3*EE) return;
    int b = idx / EE, j = idx % EE;
    const int* ni = (b==0) ? ni0 : (b==1) ? ni1 : ni2;
    const int* ei = (b==0) ? ei0 : (b==1) ? ei1 : ei2;
    int n = ni[j], e = ei[j];
    atomicAdd(&g_noff[b][n+1], 1);
    atomicAdd(&g_eoff[b][e+1], 1);
    atomicAdd(&g_Dinv[b][n], hw[e]);
}

__global__ void k_scan(){
    int bid = blockIdx.x;
    int *arr, *cur; int len;
    if (bid < 3){ arr = g_noff[bid];   cur = g_ncur[bid];   len = NN+1; }
    else        { arr = g_eoff[bid-3]; cur = g_ecur[bid-3]; len = MM+1; }
    __shared__ int sh[1024];
    int carry = 0;
    for (int base = 0; base < len; base += 1024){
        int i = base + threadIdx.x;
        int v = (i < len) ? arr[i] : 0;
        sh[threadIdx.x] = v; __syncthreads();
        for (int off = 1; off < 1024; off <<= 1){
            int t = (threadIdx.x >= off) ? sh[threadIdx.x - off] : 0;
            __syncthreads();
            sh[threadIdx.x] += t;
            __syncthreads();
        }
        int incl = sh[threadIdx.x] + carry;
        if (i < len){ arr[i] = incl; if (i < len-1) cur[i] = incl; }
        int tot = sh[1023];
        __syncthreads();
        carry += tot;
    }
}

__global__ void k_scatter(const int* __restrict__ ni0, const int* __restrict__ ei0,
                          const int* __restrict__ ni1, const int* __restrict__ ei1,
                          const int* __restrict__ ni2, const int* __restrict__ ei2){
    int idx = blockIdx.x * blockDim.x + threadIdx.x;
    if (idx >= 3*EE) return;
    int b = idx / EE, j = idx % EE;
    const int* ni = (b==0) ? ni0 : (b==1) ? ni1 : ni2;
    const int* ei = (b==0) ? ei0 : (b==1) ? ei1 : ei2;
    int n = ni[j], e = ei[j];
    int pn = atomicAdd(&g_ncur[b][n], 1); g_eiN[b][pn] = e;
    int pe = atomicAdd(&g_ecur[b][e], 1); g_niE[b][pe] = n;
}

__global__ void k_invert(){
    int i = blockIdx.x * blockDim.x + threadIdx.x;
    if (i < 3*NN){
        float d = ((float*)g_Dinv)[i];
        ((float*)g_Dinv)[i] = (d > 0.f) ? 1.f/d : 0.f;
    }
    if (i < 3*MM){
        int b = i / MM, e = i % MM;
        int c = g_eoff[b][e+1] - g_eoff[b][e];
        g_Binv[b][e] = (c > 0) ? 1.f/(float)c : 0.f;
    }
}

// ---------------- fp16 tensor-core GEMM (NN): C = act((A*ascale)@B * 1/ascale + bias) ----------------
// BM=BN=128, BK=32, 256 thr = 8 warps (4x2), warp tile 32x64, mma.m16n8k16.f16.f32acc
// ascale: power-of-two scale applied to A at fp16 pack time (lifts tiny A values
// out of fp16-subnormal range); exactly undone in the fp32 epilogue.
template<int OUTH>
__global__ void __launch_bounds__(256) k_hmma(
    const float* __restrict__ A, const float* __restrict__ B,
    void* __restrict__ Cv, const float* __restrict__ bias,
    int M, int N, int K, int ldc,
    long long sAz, long long sBz, long long sCz, long long sbz,
    int act, float ascale, float inv_ascale)
{
    __shared__ unsigned As2[16][136];   // half2: [k/2][m]
    __shared__ unsigned Bs2[16][136];   // half2: [k/2][n]
    int z = blockIdx.z;
    A += (size_t)z * sAz; B += (size_t)z * sBz;
    if (bias) bias += (size_t)z * sbz;
    int bm = blockIdx.y * 128, bn = blockIdx.x * 128;
    int tid = threadIdx.x;
    int warp = tid >> 5, lane = tid & 31;
    int wm = warp & 3, wn = warp >> 2;
    int g = lane >> 2, tg = lane & 3;

    float c[2][8][4];
    #pragma unroll
    for (int mt = 0; mt < 2; mt++)
        #pragma unroll
        for (int nt = 0; nt < 8; nt++)
            #pragma unroll
            for (int i = 0; i < 4; i++) c[mt][nt][i] = 0.f;

    for (int kt = 0; kt < K; kt += 32){
        #pragma unroll
        for (int q = tid; q < 1024; q += 256){
            int r = q >> 3, cc = (q & 7) << 2;
            float4 v = *(const float4*)(A + (size_t)(bm + r) * K + kt + cc);
            As2[(cc>>1)  ][r] = packh2(v.x*ascale, v.y*ascale);
            As2[(cc>>1)+1][r] = packh2(v.z*ascale, v.w*ascale);
        }
        #pragma unroll
        for (int q = tid; q < 1024; q += 256){
            int kk = q >> 6, n0 = (q & 63) << 1;
            float2 u0 = *(const float2*)(B + (size_t)(kt + 2*kk    ) * N + bn + n0);
            float2 u1 = *(const float2*)(B + (size_t)(kt + 2*kk + 1) * N + bn + n0);
            Bs2[kk][n0]   = packh2(u0.x, u1.x);
            Bs2[kk][n0+1] = packh2(u0.y, u1.y);
        }
        __syncthreads();

        #pragma unroll
        for (int s = 0; s < 2; s++){
            int s8 = s * 8;
            unsigned bf[8][2];
            #pragma unroll
            for (int nt = 0; nt < 8; nt++){
                int col = wn*64 + nt*8 + g;
                bf[nt][0] = Bs2[s8+tg  ][col];
                bf[nt][1] = Bs2[s8+tg+4][col];
            }
            #pragma unroll
            for (int mt = 0; mt < 2; mt++){
                int mb = wm*32 + mt*16;
                unsigned a0 = As2[s8+tg  ][mb+g];
                unsigned a1 = As2[s8+tg  ][mb+8+g];
                unsigned a2 = As2[s8+tg+4][mb+g];
                unsigned a3 = As2[s8+tg+4][mb+8+g];
                #pragma unroll
                for (int nt = 0; nt < 8; nt++){
                    asm volatile(
                        "mma.sync.aligned.m16n8k16.row.col.f32.f16.f16.f32 "
                        "{%0,%1,%2,%3}, {%4,%5,%6,%7}, {%8,%9}, {%0,%1,%2,%3};"
                        : "+f"(c[mt][nt][0]), "+f"(c[mt][nt][1]),
                          "+f"(c[mt][nt][2]), "+f"(c[mt][nt][3])
                        : "r"(a0), "r"(a1), "r"(a2), "r"(a3),
                          "r"(bf[nt][0]), "r"(bf[nt][1]));
                }
            }
        }
        __syncthreads();
    }

    #pragma unroll
    for (int mt = 0; mt < 2; mt++){
        int row0 = bm + wm*32 + mt*16 + g;
        #pragma unroll
        for (int nt = 0; nt < 8; nt++){
            int col = bn + wn*64 + nt*8 + 2*tg;
            float b0 = 0.f, b1 = 0.f;
            if (bias){ b0 = bias[col]; b1 = bias[col+1]; }
            float2 v0, v1;
            v0.x = c[mt][nt][0]*inv_ascale + b0; v0.y = c[mt][nt][1]*inv_ascale + b1;
            v1.x = c[mt][nt][2]*inv_ascale + b0; v1.y = c[mt][nt][3]*inv_ascale + b1;
            if (act){ v0.x = lk(v0.x); v0.y = lk(v0.y); v1.x = lk(v1.x); v1.y = lk(v1.y); }
            if (OUTH){
                __half* C = (__half*)Cv + (size_t)blockIdx.z * sCz;
                *(__half2*)(C + (size_t)row0 * ldc + col)       = __floats2half2_rn(v0.x, v0.y);
                *(__half2*)(C + (size_t)(row0 + 8) * ldc + col) = __floats2half2_rn(v1.x, v1.y);
            } else {
                float* C = (float*)Cv + (size_t)blockIdx.z * sCz;
                *(float2*)(C + (size_t)row0 * ldc + col)       = v0;
                *(float2*)(C + (size_t)(row0 + 8) * ldc + col) = v1;
            }
        }
    }
}

// ---------------- tf32 tensor-core GEMM (NT): C = A[M,K] @ B[N,K]^T ----------------
__global__ void __launch_bounds__(256) k_mma_nt(
    const float* __restrict__ A, const float* __restrict__ B,
    float* __restrict__ C, int M, int N, int K, int ldc,
    long long sAz, long long sBz, long long sCz)
{
    __shared__ unsigned As[16][136];
    __shared__ unsigned Bs[16][136];
    int z = blockIdx.z;
    A += (size_t)z * sAz; B += (size_t)z * sBz; C += (size_t)z * sCz;
    int bm = blockIdx.y * 128, bn = blockIdx.x * 128;
    int tid = threadIdx.x;
    int warp = tid >> 5, lane = tid & 31;
    int wm = warp & 3, wn = warp >> 2;
    int g = lane >> 2, tg = lane & 3;

    float c[2][8][4];
    #pragma unroll
    for (int mt = 0; mt < 2; mt++)
        #pragma unroll
        for (int nt = 0; nt < 8; nt++)
            #pragma unroll
            for (int i = 0; i < 4; i++) c[mt][nt][i] = 0.f;

    for (int kt = 0; kt < K; kt += 16){
        #pragma unroll
        for (int q = tid; q < 512; q += 256){
            int r = q >> 2, cc = (q & 3) << 2;
            float4 v = *(const float4*)(A + (size_t)(bm + r) * K + kt + cc);
            As[cc+0][r] = f2tf(v.x); As[cc+1][r] = f2tf(v.y);
            As[cc+2][r] = f2tf(v.z); As[cc+3][r] = f2tf(v.w);
        }
        #pragma unroll
        for (int q = tid; q < 512; q += 256){
            int r = q >> 2, cc = (q & 3) << 2;
            float4 v = *(const float4*)(B + (size_t)(bn + r) * K + kt + cc);
            Bs[cc+0][r] = f2tf(v.x); Bs[cc+1][r] = f2tf(v.y);
            Bs[cc+2][r] = f2tf(v.z); Bs[cc+3][r] = f2tf(v.w);
        }
        __syncthreads();

        #pragma unroll
        for (int ks = 0; ks < 2; ks++){
            int k0 = ks * 8;
            unsigned bf[8][2];
            #pragma unroll
            for (int nt = 0; nt < 8; nt++){
                int col = wn*64 + nt*8 + g;
                bf[nt][0] = Bs[k0+tg  ][col];
                bf[nt][1] = Bs[k0+tg+4][col];
            }
            #pragma unroll
            for (int mt = 0; mt < 2; mt++){
                int mb = wm*32 + mt*16;
                unsigned a0 = As[k0+tg  ][mb+g];
                unsigned a1 = As[k0+tg  ][mb+8+g];
                unsigned a2 = As[k0+tg+4][mb+g];
                unsigned a3 = As[k0+tg+4][mb+8+g];
                #pragma unroll
                for (int nt = 0; nt < 8; nt++){
                    asm volatile(
                        "mma.sync.aligned.m16n8k8.row.col.f32.tf32.tf32.f32 "
                        "{%0,%1,%2,%3}, {%4,%5,%6,%7}, {%8,%9}, {%0,%1,%2,%3};"
                        : "+f"(c[mt][nt][0]), "+f"(c[mt][nt][1]),
                          "+f"(c[mt][nt][2]), "+f"(c[mt][nt][3])
                        : "r"(a0), "r"(a1), "r"(a2), "r"(a3),
                          "r"(bf[nt][0]), "r"(bf[nt][1]));
                }
            }
        }
        __syncthreads();
    }

    #pragma unroll
    for (int mt = 0; mt < 2; mt++){
        int row0 = bm + wm*32 + mt*16 + g;
        #pragma unroll
        for (int nt = 0; nt < 8; nt++){
            int col = bn + wn*64 + nt*8 + 2*tg;
            float2 v0, v1;
            v0.x = c[mt][nt][0]; v0.y = c[mt][nt][1];
            v1.x = c[mt][nt][2]; v1.y = c[mt][nt][3];
            *(float2*)(C + (size_t)row0 * ldc + col)       = v0;
            *(float2*)(C + (size_t)(row0 + 8) * ldc + col) = v1;
        }
    }
}

// ---------------- w2[l][b] = Wh_l[b] @ att_l[b][256:512] (both layers) ----------------
__global__ void k_watt2(const float* __restrict__ Wh1, const float* __restrict__ at1,
                        const float* __restrict__ Wh2, const float* __restrict__ at2){
    int w = (blockIdx.x * blockDim.x + threadIdx.x) >> 5;
    int lane = threadIdx.x & 31;
    if (w >= 2*3*FF) return;
    int l = w / (3*FF);
    int b = (w / FF) % 3, k = w % FF;
    const float* Wh  = l ? Wh2 : Wh1;
    const float* att = l ? at2 : at1;
    const float* row = Wh + (size_t)b*FF*FF + (size_t)k*FF;
    const float* a2  = att + b*512 + 256;
    float4 r0 = ((const float4*)row)[lane*2], r1 = ((const float4*)row)[lane*2+1];
    float4 a0 = ((const float4*)a2 )[lane*2], a1 = ((const float4*)a2 )[lane*2+1];
    float s = r0.x*a0.x + r0.y*a0.y + r0.z*a0.z + r0.w*a0.w
            + r1.x*a1.x + r1.y*a1.y + r1.z*a1.z + r1.w*a1.w;
    #pragma unroll
    for (int o = 16; o; o >>= 1) s += __shfl_xor_sync(0xffffffffu, s, o);
    if (lane == 0) g_w2[l][b][k] = s;
}

// ---------------- s2[l][b][e] = hA[e] . w2[l][b] — one hA row read, 6 dots ----------------
__global__ void k_s2all(const float* __restrict__ hA){
    int w = (blockIdx.x * blockDim.x + threadIdx.x) >> 5;
    int lane = threadIdx.x & 31;
    if (w >= MM) return;
    int e = w;
    const float* row = hA + (size_t)e*FF;
    float4 r0 = ((const float4*)row)[lane*2], r1 = ((const float4*)row)[lane*2+1];
    #pragma unroll
    for (int q = 0; q < 6; q++){
        const float* w2 = g_w2[q/3][q%3];
        float4 a0 = ((const float4*)w2)[lane*2], a1 = ((const float4*)w2)[lane*2+1];
        float s = r0.x*a0.x + r0.y*a0.y + r0.z*a0.z + r0.w*a0.w
                + r1.x*a1.x + r1.y*a1.y + r1.z*a1.z + r1.w*a1.w;
        #pragma unroll
        for (int o = 16; o; o >>= 1) s += __shfl_xor_sync(0xffffffffu, s, o);
        if (lane == 0) g_s2[q/3][q%3][e] = s;
    }
}

// ---------------- stats: s1 + per-node softmax (max, 1/sum) -> ninfo ----------------
__global__ void k_stats(int l, const float* __restrict__ att){
    int w = (blockIdx.x * blockDim.x + threadIdx.x) >> 5;
    int lane = threadIdx.x & 31;
    if (w >= 3*NN) return;
    int b = w / NN, n = w % NN;

    const __half* xr = g_xl[b] + (size_t)n*FF;
    float4 raw = ((const float4*)xr)[lane];
    const __half2* hp = (const __half2*)&raw;
    const float* a1p = att + b*512 + lane*8;
    float4 a0 = *(const float4*)a1p, a1 = *(const float4*)(a1p+4);
    float2 f0 = __half22float2(hp[0]), f1 = __half22float2(hp[1]);
    float2 f2 = __half22float2(hp[2]), f3 = __half22float2(hp[3]);
    float s1n = f0.x*a0.x + f0.y*a0.y + f1.x*a0.z + f1.y*a0.w
              + f2.x*a1.x + f2.y*a1.y + f3.x*a1.z + f3.y*a1.w;
    #pragma unroll
    for (int o = 16; o; o >>= 1) s1n += __shfl_xor_sync(0xffffffffu, s1n, o);

    const float* s2b = g_s2[l][b];
    int beg = g_noff[b][n], end = g_noff[b][n+1];
    float mx = -1e30f;
    for (int p = beg + lane; p < end; p += 32){
        int e = g_eiN[b][p];
        mx = fmaxf(mx, lk(s1n + s2b[e]));
    }
    #pragma unroll
    for (int o = 16; o; o >>= 1) mx = fmaxf(mx, __shfl_xor_sync(0xffffffffu, mx, o));
    float sum = 0.f;
    for (int p = beg + lane; p < end; p += 32){
        int e = g_eiN[b][p];
        sum += __expf(lk(s1n + s2b[e]) - mx);
    }
    #pragma unroll
    for (int o = 16; o; o >>= 1) sum += __shfl_xor_sync(0xffffffffu, sum, o);
    if (lane == 0){
        if (end > beg) g_ninfo[b][n] = make_float4(s1n, mx, 1.f/sum, 0.f);
        else           g_ninfo[b][n] = make_float4(s1n, 0.f, 0.f, 0.f);
    }
}

// ---------------- edge pass ----------------
__global__ void k_edge(int l){
    int w = (blockIdx.x * blockDim.x + threadIdx.x) >> 5;
    int lane = threadIdx.x & 31;
    if (w >= 3*MM) return;
    int b = w / MM, e = w % MM;
    int beg = g_eoff[b][e], end = g_eoff[b][e+1];
    float s2e = g_s2[l][b][e];
    const __half* xlb = g_xl[b];
    float acc[8] = {0,0,0,0,0,0,0,0};
    for (int base = beg; base < end; base += 32){
        int p = base + lane;
        int nrow = 0; float coef = 0.f;
        if (p < end){
            nrow = g_niE[b][p];
            float4 info = g_ninfo[b][nrow];
            coef = __expf(lk(info.x + s2e) - info.y) * info.z;
        }
        int cnt = min(32, end - base);
        for (int t = 0; t < cnt; t++){
            int   r = __shfl_sync(0xffffffffu, nrow, t);
            float c = __shfl_sync(0xffffffffu, coef, t);
            float4 raw = *(const float4*)(xlb + (size_t)r * FF + lane*8);
            const __half2* hp = (const __half2*)&raw;
            float2 f0 = __half22float2(hp[0]), f1 = __half22float2(hp[1]);
            float2 f2 = __half22float2(hp[2]), f3 = __half22float2(hp[3]);
            acc[0] += c*f0.x; acc[1] += c*f0.y; acc[2] += c*f1.x; acc[3] += c*f1.y;
            acc[4] += c*f2.x; acc[5] += c*f2.y; acc[6] += c*f3.x; acc[7] += c*f3.y;
        }
    }
    float bi = g_Binv[b][e];
    __half2 o[4];
    o[0] = __floats2half2_rn(bi*acc[0], bi*acc[1]);
    o[1] = __floats2half2_rn(bi*acc[2], bi*acc[3]);
    o[2] = __floats2half2_rn(bi*acc[4], bi*acc[5]);
    o[3] = __floats2half2_rn(bi*acc[6], bi*acc[7]);
    *(float4*)(g_m[b] + (size_t)e * FF + lane*8) = *(float4*)o;
}

// ---------------- node pass ----------------
__global__ void k_node(int l, const float* __restrict__ bc, float* __restrict__ hout){
    int w = (blockIdx.x * blockDim.x + threadIdx.x) >> 5;
    int lane = threadIdx.x & 31;
    if (w >= NN) return;
    int n = w;
    float t[8] = {0,0,0,0,0,0,0,0};
    #pragma unroll
    for (int b = 0; b < 3; b++){
        int beg = g_noff[b][n], end = g_noff[b][n+1];
        float4 info = g_ninfo[b][n];
        float s1n = info.x, mxn = info.y, rsn = info.z;
        const float* s2b = g_s2[l][b];
        const __half* mb = g_m[b];
        float a[8] = {0,0,0,0,0,0,0,0};
        for (int base = beg; base < end; base += 32){
            int p = base + lane;
            int er = 0; float coef = 0.f;
            if (p < end){
                er = g_eiN[b][p];
                coef = __expf(lk(s1n + s2b[er]) - mxn) * rsn;
            }
            int cnt = min(32, end - base);
            for (int t2 = 0; t2 < cnt; t2++){
                int   r = __shfl_sync(0xffffffffu, er, t2);
                float c = __shfl_sync(0xffffffffu, coef, t2);
                float4 raw = *(const float4*)(mb + (size_t)r * FF + lane*8);
                const __half2* hp = (const __half2*)&raw;
                float2 f0 = __half22float2(hp[0]), f1 = __half22float2(hp[1]);
                float2 f2 = __half22float2(hp[2]), f3 = __half22float2(hp[3]);
                a[0] += c*f0.x; a[1] += c*f0.y; a[2] += c*f1.x; a[3] += c*f1.y;
                a[4] += c*f2.x; a[5] += c*f2.y; a[6] += c*f3.x; a[7] += c*f3.y;
            }
        }
        float di = g_Dinv[b][n];
        #pragma unroll
        for (int i = 0; i < 8; i++) t[i] += di * a[i];
    }
    #pragma unroll
    for (int k = 0; k < 3; k++){
        float4 b0 = *(const float4*)(bc + k*256 + lane*8);
        float4 b1 = *(const float4*)(bc + k*256 + lane*8 + 4);
        t[0] += b0.x; t[1] += b0.y; t[2] += b0.z; t[3] += b0.w;
        t[4] += b1.x; t[5] += b1.y; t[6] += b1.z; t[7] += b1.w;
    }
    #pragma unroll
    for (int i = 0; i < 8; i++) t[i] = lk(t[i]);
    *(float4*)(hout + (size_t)n * FF + lane*8)     = make_float4(t[0], t[1], t[2], t[3]);
    *(float4*)(hout + (size_t)n * FF + lane*8 + 4) = make_float4(t[4], t[5], t[6], t[7]);
}

// ---------------- host launcher ----------------
static void* symaddr(const void* sym){ void* p = nullptr; cudaGetSymbolAddress(&p, sym); return p; }

extern "C" void kernel_launch(void* const* d_in, const int* in_sizes, int n_in,
                              void* d_out, int out_size){
    const float* g   = (const float*)d_in[0];
    const float* x   = (const float*)d_in[1];
    const float* hw  = (const float*)d_in[2];
    const float* hA  = (const float*)d_in[3];
    const int* ni0 = (const int*)d_in[4]; const int* ei0 = (const int*)d_in[5];
    const int* ni1 = (const int*)d_in[6]; const int* ei1 = (const int*)d_in[7];
    const int* ni2 = (const int*)d_in[8]; const int* ei2 = (const int*)d_in[9];
    const float* W0  = (const float*)d_in[10]; const float* b0  = (const float*)d_in[11];
    const float* Wh1 = (const float*)d_in[12]; const float* at1 = (const float*)d_in[13];
    const float* bc1 = (const float*)d_in[14];
    const float* W1  = (const float*)d_in[15]; const float* b1  = (const float*)d_in[16];
    const float* Wh2 = (const float*)d_in[17]; const float* at2 = (const float*)d_in[18];
    const float* bc2 = (const float*)d_in[19];
    const float* Wg  = (const float*)d_in[20]; const float* bg  = (const float*)d_in[21];
    const float* Wx  = (const float*)d_in[22]; const float* bx  = (const float*)d_in[23];
    float* out = (float*)d_out;

    float* p_h    = (float*)symaddr(g_h);
    float* p_h2   = (float*)symaddr(g_h2);
    void*  p_xl   = symaddr(g_xl);
    float* p_newg = (float*)symaddr(g_newg);
    float* p_xs   = (float*)symaddr(g_xs);

    const float S1 = 1.f,    IS1 = 1.f;
    const float SK = 1024.f, ISK = 1.f/1024.f;   // for small-magnitude hconv outputs

    // ---- setup: CSR build + h-independent attention terms ----
    k_zero<<<(3*(MM+1) + 255)/256, 256>>>();
    k_hist<<<(3*EE + 255)/256, 256>>>(ni0, ei0, ni1, ei1, ni2, ei2, hw);
    k_scan<<<6, 1024>>>();
    k_scatter<<<(3*EE + 255)/256, 256>>>(ni0, ei0, ni1, ei1, ni2, ei2);
    k_invert<<<(3*MM + 255)/256, 256>>>();
    k_watt2<<<(2*3*FF*32 + 255)/256, 256>>>(Wh1, at1, Wh2, at2);
    k_s2all<<<(MM*32 + 255)/256, 256>>>(hA);

    // ---- layer0: A = g ~ O(1) ----
    k_hmma<0><<<dim3(2,32,3), 256>>>(g, W0, p_h, b0, 4096, 256, 256, 256,
                                     (long long)4096*256, 65536LL, (long long)4096*256, 256LL, 1, S1, IS1);

    // ---- hyper1: A = h (O(1)) ----
    k_hmma<1><<<dim3(2,96,3), 256>>>(p_h, Wh1, p_xl, nullptr, 12288, 256, 256, 256,
                                     0LL, 65536LL, (long long)12288*256, 0LL, 0, S1, IS1);
    k_stats<<<(3*NN*32 + 255)/256, 256>>>(0, at1);
    k_edge<<<(3*MM*32 + 255)/256, 256>>>(0);
    k_node<<<(NN*32 + 255)/256, 256>>>(0, bc1, p_h);

    // ---- layer1: A = hconv1 output (small) -> scale 1024 ----
    k_hmma<0><<<dim3(2,32,3), 256>>>(p_h, W1, p_h2, b1, 4096, 256, 256, 256,
                                     (long long)4096*256, 65536LL, (long long)4096*256, 256LL, 1, SK, ISK);

    // ---- hyper2: A = h2 (small) -> scale 1024 ----
    k_hmma<1><<<dim3(2,96,3), 256>>>(p_h2, Wh2, p_xl, nullptr, 12288, 256, 256, 256,
                                     0LL, 65536LL, (long long)12288*256, 0LL, 0, SK, ISK);
    k_stats<<<(3*NN*32 + 255)/256, 256>>>(1, at2);
    k_edge<<<(3*MM*32 + 255)/256, 256>>>(1);
    k_node<<<(NN*32 + 255)/256, 256>>>(1, bc2, out + HOFF);

    // ---- projections: new_g A = hconv2 output (very small) -> scale 1024 ----
    k_hmma<0><<<dim3(1,32,2), 256>>>(out + HOFF + (size_t)4096*256, Wg + 32768, p_newg, bg + 128,
                                     4096, 128, 256, 128,
                                     (long long)4096*256, 32768LL, (long long)4096*128, 128LL, 1, SK, ISK);
    // xs: A = x ~ O(1)
    k_hmma<0><<<dim3(1,32,2), 256>>>(x, Wx + 32768, p_xs, bx + 128,
                                     4096, 128, 256, 128,
                                     0LL, 32768LL, (long long)4096*128, 128LL, 1, S1, IS1);

    // ---- result: [xs1@newg1^T | xs2@newg2^T] (tf32 — e8 exponent handles tiny newg) ----
    k_mma_nt<<<dim3(32,32,2), 256>>>(p_xs, p_newg, out, 4096, 4096, 128, 8192,
                                     (long long)4096*128, (long long)4096*128, 4096LL);
}

// round 6
// speedup vs baseline: 2.5876x; 1.0931x over previous
#include <cuda_runtime.h>
#include <cuda_fp16.h>
#include <math.h>

#define NN 12288
#define SS 4096
#define MM 16384
#define EE 393216
#define FF 256
#define CC 128
#define SLOPE 0.2f
#define HOFF 33554432   // 4096*8192, h output starts here

// ---------------- scratch (static device memory; no allocation) ----------------
__device__ float  g_h  [NN*FF];
__device__ float  g_h2 [NN*FF];
__device__ __half g_xl [3][NN*FF];    // fp16 rows for gather (layer1: scaled x1024)
__device__ __half g_m  [3][MM*FF];    // fp16 rows for gather (layer1: scaled x1024)
__device__ float  g_w2 [2][3][FF];
__device__ float  g_s2 [2][3][MM];
__device__ float4 g_ninfo[3][NN];     // (s1, max, 1/sum, _)
__device__ int    g_noff[3][NN+1];
__device__ int    g_eoff[3][MM+1];
__device__ int    g_ncur[3][NN];
__device__ int    g_ecur[3][MM];
__device__ int    g_eiN [3][EE];
__device__ int    g_niE [3][EE];
__device__ float  g_Dinv[3][NN];
__device__ float  g_Binv[3][MM];
__device__ __half g_newgh[2][SS*CC];  // scaled x1024
__device__ __half g_xsh  [2][SS*CC];

__device__ __forceinline__ float lk(float v){ return v >= 0.f ? v : SLOPE * v; }
__device__ __forceinline__ unsigned packh2(float x, float y){
    __half2 h = __floats2half2_rn(x, y);
    return *(unsigned*)&h;
}

// ---------------- setup: counting-sort CSR build ----------------
__global__ void k_zero(){
    int i = blockIdx.x * blockDim.x + threadIdx.x;
    if (i < 3*(NN+1)) ((int*)g_noff)[i] = 0;
    if (i < 3*(MM+1)) ((int*)g_eoff)[i] = 0;
    if (i < 3*NN)     ((float*)g_Dinv)[i] = 0.f;
}

__global__ void k_hist(const int* __restrict__ ni0, const int* __restrict__ ei0,
                       const int* __restrict__ ni1, const int* __restrict__ ei1,
                       const int* __restrict__ ni2, const int* __restrict__ ei2,
                       const float* __restrict__ hw){
    int idx = blockIdx.x * blockDim.x + threadIdx.x;
    if (idx >= 3*EE) return;
    int b = idx / EE, j = idx % EE;
    const int* ni = (b==0) ? ni0 : (b==1) ? ni1 : ni2;
    const int* ei = (b==0) ? ei0 : (b==1) ? ei1 : ei2;
    int n = ni[j], e = ei[j];
    atomicAdd(&g_noff[b][n+1], 1);
    atomicAdd(&g_eoff[b][e+1], 1);
    atomicAdd(&g_Dinv[b][n], hw[e]);
}

__global__ void k_scan(){
    int bid = blockIdx.x;
    int *arr, *cur; int len;
    if (bid < 3){ arr = g_noff[bid];   cur = g_ncur[bid];   len = NN+1; }
    else        { arr = g_eoff[bid-3]; cur = g_ecur[bid-3]; len = MM+1; }
    __shared__ int sh[1024];
    int carry = 0;
    for (int base = 0; base < len; base += 1024){
        int i = base + threadIdx.x;
        int v = (i < len) ? arr[i] : 0;
        sh[threadIdx.x] = v; __syncthreads();
        for (int off = 1; off < 1024; off <<= 1){
            int t = (threadIdx.x >= off) ? sh[threadIdx.x - off] : 0;
            __syncthreads();
            sh[threadIdx.x] += t;
            __syncthreads();
        }
        int incl = sh[threadIdx.x] + carry;
        if (i < len){ arr[i] = incl; if (i < len-1) cur[i] = incl; }
        int tot = sh[1023];
        __syncthreads();
        carry += tot;
    }
}

__global__ void k_scatter(const int* __restrict__ ni0, const int* __restrict__ ei0,
                          const int* __restrict__ ni1, const int* __restrict__ ei1,
                          const int* __restrict__ ni2, const int* __restrict__ ei2){
    int idx = blockIdx.x * blockDim.x + threadIdx.x;
    if (idx >= 3*EE) return;
    int b = idx / EE, j = idx % EE;
    const int* ni = (b==0) ? ni0 : (b==1) ? ni1 : ni2;
    const int* ei = (b==0) ? ei0 : (b==1) ? ei1 : ei2;
    int n = ni[j], e = ei[j];
    int pn = atomicAdd(&g_ncur[b][n], 1); g_eiN[b][pn] = e;
    int pe = atomicAdd(&g_ecur[b][e], 1); g_niE[b][pe] = n;
}

__global__ void k_invert(){
    int i = blockIdx.x * blockDim.x + threadIdx.x;
    if (i < 3*NN){
        float d = ((float*)g_Dinv)[i];
        ((float*)g_Dinv)[i] = (d > 0.f) ? 1.f/d : 0.f;
    }
    if (i < 3*MM){
        int b = i / MM, e = i % MM;
        int c = g_eoff[b][e+1] - g_eoff[b][e];
        g_Binv[b][e] = (c > 0) ? 1.f/(float)c : 0.f;
    }
}

// ---------------- fp16 tensor-core GEMM (NN), register double-buffered ----------------
// C = act((A*ascale)@B)*inv_ascale + bias; OUTH=1 -> half output, value*oscale
template<int OUTH>
__global__ void __launch_bounds__(256) k_hmma(
    const float* __restrict__ A, const float* __restrict__ B,
    void* __restrict__ Cv, const float* __restrict__ bias,
    int M, int N, int K, int ldc,
    long long sAz, long long sBz, long long sCz, long long sbz,
    int act, float ascale, float inv_ascale, float oscale)
{
    __shared__ unsigned As2[16][136];
    __shared__ unsigned Bs2[16][136];
    int z = blockIdx.z;
    A += (size_t)z * sAz; B += (size_t)z * sBz;
    if (bias) bias += (size_t)z * sbz;
    int bm = blockIdx.y * 128, bn = blockIdx.x * 128;
    int tid = threadIdx.x;
    int warp = tid >> 5, lane = tid & 31;
    int wm = warp & 3, wn = warp >> 2;
    int g = lane >> 2, tg = lane & 3;

    float c[2][8][4];
    #pragma unroll
    for (int mt = 0; mt < 2; mt++)
        #pragma unroll
        for (int nt = 0; nt < 8; nt++)
            #pragma unroll
            for (int i = 0; i < 4; i++) c[mt][nt][i] = 0.f;

    float4 va[4]; float2 vb0[4], vb1[4];
    // prologue loads (kt = 0)
    #pragma unroll
    for (int i = 0; i < 4; i++){
        int q = tid + 256*i;
        int r = q >> 3, cc = (q & 7) << 2;
        va[i] = *(const float4*)(A + (size_t)(bm + r) * K + cc);
    }
    #pragma unroll
    for (int i = 0; i < 4; i++){
        int q = tid + 256*i;
        int kk = q >> 6, n0 = (q & 63) << 1;
        vb0[i] = *(const float2*)(B + (size_t)(2*kk    ) * N + bn + n0);
        vb1[i] = *(const float2*)(B + (size_t)(2*kk + 1) * N + bn + n0);
    }

    for (int kt = 0; kt < K; kt += 32){
        #pragma unroll
        for (int i = 0; i < 4; i++){
            int q = tid + 256*i;
            int r = q >> 3, cc = (q & 7) << 2;
            As2[(cc>>1)  ][r] = packh2(va[i].x*ascale, va[i].y*ascale);
            As2[(cc>>1)+1][r] = packh2(va[i].z*ascale, va[i].w*ascale);
        }
        #pragma unroll
        for (int i = 0; i < 4; i++){
            int q = tid + 256*i;
            int kk = q >> 6, n0 = (q & 63) << 1;
            Bs2[kk][n0]   = packh2(vb0[i].x, vb1[i].x);
            Bs2[kk][n0+1] = packh2(vb0[i].y, vb1[i].y);
        }
        __syncthreads();
        if (kt + 32 < K){
            #pragma unroll
            for (int i = 0; i < 4; i++){
                int q = tid + 256*i;
                int r = q >> 3, cc = (q & 7) << 2;
                va[i] = *(const float4*)(A + (size_t)(bm + r) * K + kt + 32 + cc);
            }
            #pragma unroll
            for (int i = 0; i < 4; i++){
                int q = tid + 256*i;
                int kk = q >> 6, n0 = (q & 63) << 1;
                vb0[i] = *(const float2*)(B + (size_t)(kt + 32 + 2*kk    ) * N + bn + n0);
                vb1[i] = *(const float2*)(B + (size_t)(kt + 32 + 2*kk + 1) * N + bn + n0);
            }
        }

        #pragma unroll
        for (int s = 0; s < 2; s++){
            int s8 = s * 8;
            unsigned bf[8][2];
            #pragma unroll
            for (int nt = 0; nt < 8; nt++){
                int col = wn*64 + nt*8 + g;
                bf[nt][0] = Bs2[s8+tg  ][col];
                bf[nt][1] = Bs2[s8+tg+4][col];
            }
            #pragma unroll
            for (int mt = 0; mt < 2; mt++){
                int mb = wm*32 + mt*16;
                unsigned a0 = As2[s8+tg  ][mb+g];
                unsigned a1 = As2[s8+tg  ][mb+8+g];
                unsigned a2 = As2[s8+tg+4][mb+g];
                unsigned a3 = As2[s8+tg+4][mb+8+g];
                #pragma unroll
                for (int nt = 0; nt < 8; nt++){
                    asm volatile(
                        "mma.sync.aligned.m16n8k16.row.col.f32.f16.f16.f32 "
                        "{%0,%1,%2,%3}, {%4,%5,%6,%7}, {%8,%9}, {%0,%1,%2,%3};"
                        : "+f"(c[mt][nt][0]), "+f"(c[mt][nt][1]),
                          "+f"(c[mt][nt][2]), "+f"(c[mt][nt][3])
                        : "r"(a0), "r"(a1), "r"(a2), "r"(a3),
                          "r"(bf[nt][0]), "r"(bf[nt][1]));
                }
            }
        }
        __syncthreads();
    }

    #pragma unroll
    for (int mt = 0; mt < 2; mt++){
        int row0 = bm + wm*32 + mt*16 + g;
        #pragma unroll
        for (int nt = 0; nt < 8; nt++){
            int col = bn + wn*64 + nt*8 + 2*tg;
            float b0 = 0.f, b1 = 0.f;
            if (bias){ b0 = bias[col]; b1 = bias[col+1]; }
            float2 v0, v1;
            v0.x = c[mt][nt][0]*inv_ascale + b0; v0.y = c[mt][nt][1]*inv_ascale + b1;
            v1.x = c[mt][nt][2]*inv_ascale + b0; v1.y = c[mt][nt][3]*inv_ascale + b1;
            if (act){ v0.x = lk(v0.x); v0.y = lk(v0.y); v1.x = lk(v1.x); v1.y = lk(v1.y); }
            if (OUTH){
                __half* C = (__half*)Cv + (size_t)blockIdx.z * sCz;
                *(__half2*)(C + (size_t)row0 * ldc + col)       = __floats2half2_rn(v0.x*oscale, v0.y*oscale);
                *(__half2*)(C + (size_t)(row0 + 8) * ldc + col) = __floats2half2_rn(v1.x*oscale, v1.y*oscale);
            } else {
                float* C = (float*)Cv + (size_t)blockIdx.z * sCz;
                *(float2*)(C + (size_t)row0 * ldc + col)       = v0;
                *(float2*)(C + (size_t)(row0 + 8) * ldc + col) = v1;
            }
        }
    }
}

// ---------------- fp16-input NT GEMM: C = (A[M,K] @ B[N,K]^T) * oscale ----------------
__global__ void __launch_bounds__(256) k_hmma_nt(
    const __half* __restrict__ A, const __half* __restrict__ B,
    float* __restrict__ C, int M, int N, int K, int ldc,
    long long sAz, long long sBz, long long sCz, float oscale)
{
    __shared__ unsigned As2[16][136];
    __shared__ unsigned Bs2[16][136];
    int z = blockIdx.z;
    A += (size_t)z * sAz; B += (size_t)z * sBz; C += (size_t)z * sCz;
    int bm = blockIdx.y * 128, bn = blockIdx.x * 128;
    int tid = threadIdx.x;
    int warp = tid >> 5, lane = tid & 31;
    int wm = warp & 3, wn = warp >> 2;
    int g = lane >> 2, tg = lane & 3;

    float c[2][8][4];
    #pragma unroll
    for (int mt = 0; mt < 2; mt++)
        #pragma unroll
        for (int nt = 0; nt < 8; nt++)
            #pragma unroll
            for (int i = 0; i < 4; i++) c[mt][nt][i] = 0.f;

    float4 va[2], vb[2];
    #pragma unroll
    for (int i = 0; i < 2; i++){
        int q = tid + 256*i;
        int r = q >> 2, cc = (q & 3) << 3;    // 8 halves per float4
        va[i] = *(const float4*)(A + (size_t)(bm + r) * K + cc);
        vb[i] = *(const float4*)(B + (size_t)(bn + r) * K + cc);
    }

    for (int kt = 0; kt < K; kt += 32){
        #pragma unroll
        for (int i = 0; i < 2; i++){
            int q = tid + 256*i;
            int r = q >> 2, cc = (q & 3) << 3;
            const unsigned* pa = (const unsigned*)&va[i];
            const unsigned* pb = (const unsigned*)&vb[i];
            int kh = cc >> 1;                  // half2 index
            As2[kh  ][r] = pa[0]; As2[kh+1][r] = pa[1];
            As2[kh+2][r] = pa[2]; As2[kh+3][r] = pa[3];
            Bs2[kh  ][r] = pb[0]; Bs2[kh+1][r] = pb[1];
            Bs2[kh+2][r] = pb[2]; Bs2[kh+3][r] = pb[3];
        }
        __syncthreads();
        if (kt + 32 < K){
            #pragma unroll
            for (int i = 0; i < 2; i++){
                int q = tid + 256*i;
                int r = q >> 2, cc = (q & 3) << 3;
                va[i] = *(const float4*)(A + (size_t)(bm + r) * K + kt + 32 + cc);
                vb[i] = *(const float4*)(B + (size_t)(bn + r) * K + kt + 32 + cc);
            }
        }

        #pragma unroll
        for (int s = 0; s < 2; s++){
            int s8 = s * 8;
            unsigned bf[8][2];
            #pragma unroll
            for (int nt = 0; nt < 8; nt++){
                int col = wn*64 + nt*8 + g;
                bf[nt][0] = Bs2[s8+tg  ][col];
                bf[nt][1] = Bs2[s8+tg+4][col];
            }
            #pragma unroll
            for (int mt = 0; mt < 2; mt++){
                int mb = wm*32 + mt*16;
                unsigned a0 = As2[s8+tg  ][mb+g];
                unsigned a1 = As2[s8+tg  ][mb+8+g];
                unsigned a2 = As2[s8+tg+4][mb+g];
                unsigned a3 = As2[s8+tg+4][mb+8+g];
                #pragma unroll
                for (int nt = 0; nt < 8; nt++){
                    asm volatile(
                        "mma.sync.aligned.m16n8k16.row.col.f32.f16.f16.f32 "
                        "{%0,%1,%2,%3}, {%4,%5,%6,%7}, {%8,%9}, {%0,%1,%2,%3};"
                        : "+f"(c[mt][nt][0]), "+f"(c[mt][nt][1]),
                          "+f"(c[mt][nt][2]), "+f"(c[mt][nt][3])
                        : "r"(a0), "r"(a1), "r"(a2), "r"(a3),
                          "r"(bf[nt][0]), "r"(bf[nt][1]));
                }
            }
        }
        __syncthreads();
    }

    #pragma unroll
    for (int mt = 0; mt < 2; mt++){
        int row0 = bm + wm*32 + mt*16 + g;
        #pragma unroll
        for (int nt = 0; nt < 8; nt++){
            int col = bn + wn*64 + nt*8 + 2*tg;
            float2 v0, v1;
            v0.x = c[mt][nt][0]*oscale; v0.y = c[mt][nt][1]*oscale;
            v1.x = c[mt][nt][2]*oscale; v1.y = c[mt][nt][3]*oscale;
            *(float2*)(C + (size_t)row0 * ldc + col)       = v0;
            *(float2*)(C + (size_t)(row0 + 8) * ldc + col) = v1;
        }
    }
}

// ---------------- w2[l][b] = Wh_l[b] @ att_l[b][256:512] ----------------
__global__ void k_watt2(const float* __restrict__ Wh1, const float* __restrict__ at1,
                        const float* __restrict__ Wh2, const float* __restrict__ at2){
    int w = (blockIdx.x * blockDim.x + threadIdx.x) >> 5;
    int lane = threadIdx.x & 31;
    if (w >= 2*3*FF) return;
    int l = w / (3*FF);
    int b = (w / FF) % 3, k = w % FF;
    const float* Wh  = l ? Wh2 : Wh1;
    const float* att = l ? at2 : at1;
    const float* row = Wh + (size_t)b*FF*FF + (size_t)k*FF;
    const float* a2  = att + b*512 + 256;
    float4 r0 = ((const float4*)row)[lane*2], r1 = ((const float4*)row)[lane*2+1];
    float4 a0 = ((const float4*)a2 )[lane*2], a1 = ((const float4*)a2 )[lane*2+1];
    float s = r0.x*a0.x + r0.y*a0.y + r0.z*a0.z + r0.w*a0.w
            + r1.x*a1.x + r1.y*a1.y + r1.z*a1.z + r1.w*a1.w;
    #pragma unroll
    for (int o = 16; o; o >>= 1) s += __shfl_xor_sync(0xffffffffu, s, o);
    if (lane == 0) g_w2[l][b][k] = s;
}

// ---------------- s2[l][b][e] = hA[e] . w2[l][b] ----------------
__global__ void k_s2all(const float* __restrict__ hA){
    int w = (blockIdx.x * blockDim.x + threadIdx.x) >> 5;
    int lane = threadIdx.x & 31;
    if (w >= MM) return;
    int e = w;
    const float* row = hA + (size_t)e*FF;
    float4 r0 = ((const float4*)row)[lane*2], r1 = ((const float4*)row)[lane*2+1];
    #pragma unroll
    for (int q = 0; q < 6; q++){
        const float* w2 = g_w2[q/3][q%3];
        float4 a0 = ((const float4*)w2)[lane*2], a1 = ((const float4*)w2)[lane*2+1];
        float s = r0.x*a0.x + r0.y*a0.y + r0.z*a0.z + r0.w*a0.w
                + r1.x*a1.x + r1.y*a1.y + r1.z*a1.z + r1.w*a1.w;
        #pragma unroll
        for (int o = 16; o; o >>= 1) s += __shfl_xor_sync(0xffffffffu, s, o);
        if (lane == 0) g_s2[q/3][q%3][e] = s;
    }
}

// ---------------- stats (xl may be stored scaled; invS descale) ----------------
__global__ void k_stats(int l, const float* __restrict__ att, float invS){
    int w = (blockIdx.x * blockDim.x + threadIdx.x) >> 5;
    int lane = threadIdx.x & 31;
    if (w >= 3*NN) return;
    int b = w / NN, n = w % NN;

    const __half* xr = g_xl[b] + (size_t)n*FF;
    float4 raw = ((const float4*)xr)[lane];
    const __half2* hp = (const __half2*)&raw;
    const float* a1p = att + b*512 + lane*8;
    float4 a0 = *(const float4*)a1p, a1 = *(const float4*)(a1p+4);
    float2 f0 = __half22float2(hp[0]), f1 = __half22float2(hp[1]);
    float2 f2 = __half22float2(hp[2]), f3 = __half22float2(hp[3]);
    float s1n = f0.x*a0.x + f0.y*a0.y + f1.x*a0.z + f1.y*a0.w
              + f2.x*a1.x + f2.y*a1.y + f3.x*a1.z + f3.y*a1.w;
    #pragma unroll
    for (int o = 16; o; o >>= 1) s1n += __shfl_xor_sync(0xffffffffu, s1n, o);
    s1n *= invS;

    const float* s2b = g_s2[l][b];
    int beg = g_noff[b][n], end = g_noff[b][n+1];
    float mx = -1e30f;
    for (int p = beg + lane; p < end; p += 32){
        int e = g_eiN[b][p];
        mx = fmaxf(mx, lk(s1n + s2b[e]));
    }
    #pragma unroll
    for (int o = 16; o; o >>= 1) mx = fmaxf(mx, __shfl_xor_sync(0xffffffffu, mx, o));
    float sum = 0.f;
    for (int p = beg + lane; p < end; p += 32){
        int e = g_eiN[b][p];
        sum += __expf(lk(s1n + s2b[e]) - mx);
    }
    #pragma unroll
    for (int o = 16; o; o >>= 1) sum += __shfl_xor_sync(0xffffffffu, sum, o);
    if (lane == 0){
        if (end > beg) g_ninfo[b][n] = make_float4(s1n, mx, 1.f/sum, 0.f);
        else           g_ninfo[b][n] = make_float4(s1n, 0.f, 0.f, 0.f);
    }
}

// ---------------- edge pass (m inherits xl's scale) ----------------
__global__ void k_edge(int l){
    int w = (blockIdx.x * blockDim.x + threadIdx.x) >> 5;
    int lane = threadIdx.x & 31;
    if (w >= 3*MM) return;
    int b = w / MM, e = w % MM;
    int beg = g_eoff[b][e], end = g_eoff[b][e+1];
    float s2e = g_s2[l][b][e];
    const __half* xlb = g_xl[b];
    float acc[8] = {0,0,0,0,0,0,0,0};
    for (int base = beg; base < end; base += 32){
        int p = base + lane;
        int nrow = 0; float coef = 0.f;
        if (p < end){
            nrow = g_niE[b][p];
            float4 info = g_ninfo[b][nrow];
            coef = __expf(lk(info.x + s2e) - info.y) * info.z;
        }
        int cnt = min(32, end - base);
        for (int t = 0; t < cnt; t++){
            int   r = __shfl_sync(0xffffffffu, nrow, t);
            float c = __shfl_sync(0xffffffffu, coef, t);
            float4 raw = *(const float4*)(xlb + (size_t)r * FF + lane*8);
            const __half2* hp = (const __half2*)&raw;
            float2 f0 = __half22float2(hp[0]), f1 = __half22float2(hp[1]);
            float2 f2 = __half22float2(hp[2]), f3 = __half22float2(hp[3]);
            acc[0] += c*f0.x; acc[1] += c*f0.y; acc[2] += c*f1.x; acc[3] += c*f1.y;
            acc[4] += c*f2.x; acc[5] += c*f2.y; acc[6] += c*f3.x; acc[7] += c*f3.y;
        }
    }
    float bi = g_Binv[b][e];
    __half2 o[4];
    o[0] = __floats2half2_rn(bi*acc[0], bi*acc[1]);
    o[1] = __floats2half2_rn(bi*acc[2], bi*acc[3]);
    o[2] = __floats2half2_rn(bi*acc[4], bi*acc[5]);
    o[3] = __floats2half2_rn(bi*acc[6], bi*acc[7]);
    *(float4*)(g_m[b] + (size_t)e * FF + lane*8) = *(float4*)o;
}

// ---------------- node pass (descale by invS before bias) ----------------
__global__ void k_node(int l, const float* __restrict__ bc, float* __restrict__ hout, float invS){
    int w = (blockIdx.x * blockDim.x + threadIdx.x) >> 5;
    int lane = threadIdx.x & 31;
    if (w >= NN) return;
    int n = w;
    float t[8] = {0,0,0,0,0,0,0,0};
    #pragma unroll
    for (int b = 0; b < 3; b++){
        int beg = g_noff[b][n], end = g_noff[b][n+1];
        float4 info = g_ninfo[b][n];
        float s1n = info.x, mxn = info.y, rsn = info.z;
        const float* s2b = g_s2[l][b];
        const __half* mb = g_m[b];
        float a[8] = {0,0,0,0,0,0,0,0};
        for (int base = beg; base < end; base += 32){
            int p = base + lane;
            int er = 0; float coef = 0.f;
            if (p < end){
                er = g_eiN[b][p];
                coef = __expf(lk(s1n + s2b[er]) - mxn) * rsn;
            }
            int cnt = min(32, end - base);
            for (int t2 = 0; t2 < cnt; t2++){
                int   r = __shfl_sync(0xffffffffu, er, t2);
                float c = __shfl_sync(0xffffffffu, coef, t2);
                float4 raw = *(const float4*)(mb + (size_t)r * FF + lane*8);
                const __half2* hp = (const __half2*)&raw;
                float2 f0 = __half22float2(hp[0]), f1 = __half22float2(hp[1]);
                float2 f2 = __half22float2(hp[2]), f3 = __half22float2(hp[3]);
                a[0] += c*f0.x; a[1] += c*f0.y; a[2] += c*f1.x; a[3] += c*f1.y;
                a[4] += c*f2.x; a[5] += c*f2.y; a[6] += c*f3.x; a[7] += c*f3.y;
            }
        }
        float di = g_Dinv[b][n];
        #pragma unroll
        for (int i = 0; i < 8; i++) t[i] += di * a[i];
    }
    #pragma unroll
    for (int i = 0; i < 8; i++) t[i] *= invS;
    #pragma unroll
    for (int k = 0; k < 3; k++){
        float4 b0 = *(const float4*)(bc + k*256 + lane*8);
        float4 b1 = *(const float4*)(bc + k*256 + lane*8 + 4);
        t[0] += b0.x; t[1] += b0.y; t[2] += b0.z; t[3] += b0.w;
        t[4] += b1.x; t[5] += b1.y; t[6] += b1.z; t[7] += b1.w;
    }
    #pragma unroll
    for (int i = 0; i < 8; i++) t[i] = lk(t[i]);
    *(float4*)(hout + (size_t)n * FF + lane*8)     = make_float4(t[0], t[1], t[2], t[3]);
    *(float4*)(hout + (size_t)n * FF + lane*8 + 4) = make_float4(t[4], t[5], t[6], t[7]);
}

// ---------------- host launcher ----------------
static void* symaddr(const void* sym){ void* p = nullptr; cudaGetSymbolAddress(&p, sym); return p; }

extern "C" void kernel_launch(void* const* d_in, const int* in_sizes, int n_in,
                              void* d_out, int out_size){
    const float* g   = (const float*)d_in[0];
    const float* x   = (const float*)d_in[1];
    const float* hw  = (const float*)d_in[2];
    const float* hA  = (const float*)d_in[3];
    const int* ni0 = (const int*)d_in[4]; const int* ei0 = (const int*)d_in[5];
    const int* ni1 = (const int*)d_in[6]; const int* ei1 = (const int*)d_in[7];
    const int* ni2 = (const int*)d_in[8]; const int* ei2 = (const int*)d_in[9];
    const float* W0  = (const float*)d_in[10]; const float* b0  = (const float*)d_in[11];
    const float* Wh1 = (const float*)d_in[12]; const float* at1 = (const float*)d_in[13];
    const float* bc1 = (const float*)d_in[14];
    const float* W1  = (const float*)d_in[15]; const float* b1  = (const float*)d_in[16];
    const float* Wh2 = (const float*)d_in[17]; const float* at2 = (const float*)d_in[18];
    const float* bc2 = (const float*)d_in[19];
    const float* Wg  = (const float*)d_in[20]; const float* bg  = (const float*)d_in[21];
    const float* Wx  = (const float*)d_in[22]; const float* bx  = (const float*)d_in[23];
    float* out = (float*)d_out;

    float*  p_h     = (float*)symaddr(g_h);
    float*  p_h2    = (float*)symaddr(g_h2);
    void*   p_xl    = symaddr(g_xl);
    void*   p_newgh = symaddr(g_newgh);
    void*   p_xsh   = symaddr(g_xsh);

    const float S1 = 1.f,    IS1 = 1.f;
    const float SK = 1024.f, ISK = 1.f/1024.f;

    // fork a side stream for input-only work (CSR build, attention terms, xs)
    cudaStream_t sB = 0;
    cudaEvent_t evF = 0, evJ = 0;
    cudaStreamCreateWithFlags(&sB, cudaStreamNonBlocking);
    cudaEventCreateWithFlags(&evF, cudaEventDisableTiming);
    cudaEventCreateWithFlags(&evJ, cudaEventDisableTiming);

    cudaEventRecord(evF, 0);
    cudaStreamWaitEvent(sB, evF, 0);

    // ---- side stream: setup + h-independent terms + xs projection ----
    k_zero<<<(3*(MM+1) + 255)/256, 256, 0, sB>>>();
    k_hist<<<(3*EE + 255)/256, 256, 0, sB>>>(ni0, ei0, ni1, ei1, ni2, ei2, hw);
    k_scan<<<6, 1024, 0, sB>>>();
    k_scatter<<<(3*EE + 255)/256, 256, 0, sB>>>(ni0, ei0, ni1, ei1, ni2, ei2);
    k_invert<<<(3*MM + 255)/256, 256, 0, sB>>>();
    k_watt2<<<(2*3*FF*32 + 255)/256, 256, 0, sB>>>(Wh1, at1, Wh2, at2);
    k_s2all<<<(MM*32 + 255)/256, 256, 0, sB>>>(hA);
    k_hmma<1><<<dim3(1,32,2), 256, 0, sB>>>(x, Wx + 32768, p_xsh, bx + 128,
                                            4096, 128, 256, 128,
                                            0LL, 32768LL, (long long)4096*128, 128LL, 1, S1, IS1, 1.f);
    cudaEventRecord(evJ, sB);

    // ---- main stream: layer0 + hyper1-lin GEMMs (independent of setup) ----
    k_hmma<0><<<dim3(2,32,3), 256>>>(g, W0, p_h, b0, 4096, 256, 256, 256,
                                     (long long)4096*256, 65536LL, (long long)4096*256, 256LL, 1, S1, IS1, 1.f);
    k_hmma<1><<<dim3(2,96,3), 256>>>(p_h, Wh1, p_xl, nullptr, 12288, 256, 256, 256,
                                     0LL, 65536LL, (long long)12288*256, 0LL, 0, S1, IS1, 1.f);
    cudaStreamWaitEvent(0, evJ, 0);   // join: stats needs CSR + s2 + xl

    // ---- hyper1 ----
    k_stats<<<(3*NN*32 + 255)/256, 256>>>(0, at1, IS1);
    k_edge<<<(3*MM*32 + 255)/256, 256>>>(0);
    k_node<<<(NN*32 + 255)/256, 256>>>(0, bc1, p_h, IS1);

    // ---- layer1 (A small -> ascale 1024) ----
    k_hmma<0><<<dim3(2,32,3), 256>>>(p_h, W1, p_h2, b1, 4096, 256, 256, 256,
                                     (long long)4096*256, 65536LL, (long long)4096*256, 256LL, 1, SK, ISK, 1.f);

    // ---- hyper2: xl stored scaled x1024 (true values ~3e-5, below fp16 normal floor) ----
    k_hmma<1><<<dim3(2,96,3), 256>>>(p_h2, Wh2, p_xl, nullptr, 12288, 256, 256, 256,
                                     0LL, 65536LL, (long long)12288*256, 0LL, 0, SK, ISK, 1024.f);
    k_stats<<<(3*NN*32 + 255)/256, 256>>>(1, at2, ISK);
    k_edge<<<(3*MM*32 + 255)/256, 256>>>(1);
    k_node<<<(NN*32 + 255)/256, 256>>>(1, bc2, out + HOFF, ISK);

    // ---- new_g projection (segments 1,2), stored as fp16 scaled x1024 ----
    k_hmma<1><<<dim3(1,32,2), 256>>>(out + HOFF + (size_t)4096*256, Wg + 32768, p_newgh, bg + 128,
                                     4096, 128, 256, 128,
                                     (long long)4096*256, 32768LL, (long long)4096*128, 128LL, 1, SK, ISK, 1024.f);

    // ---- result: [xs1@newg1^T | xs2@newg2^T], fp16 inputs, descale 1/1024 ----
    k_hmma_nt<<<dim3(32,32,2), 256>>>((const __half*)p_xsh, (const __half*)p_newgh, out,
                                      4096, 4096, 128, 8192,
                                      (long long)4096*128, (long long)4096*128, 4096LL, ISK);
}